// round 11
// baseline (speedup 1.0000x reference)
#include <cuda_runtime.h>
#include <cuda_fp16.h>
#include <cstdint>

#define NLAYERS 2
#define NB 4
#define BS 256
#define NHID 1024
#define NINP 1024
#define NTOK 32000
#define T 64
#define B 64
#define DK 16
#define NCTA 128

// ---------------- scratch (device globals: no allocation allowed) ----------
__device__ float g_xbuf[2][(size_t)T * B * NHID];
__device__ float g_xg[(size_t)T * B * NB * 4 * BS];
__device__ float g_h[B * NHID];
__device__ float g_hl[B * NHID];
__device__ unsigned g_flags[NCTA * 32];               // one flag per 128B line
__device__ unsigned g_epoch[32];                      // single epoch line
__device__ unsigned short g_wh[(size_t)NTOK * NHID];  // Wd fp16 hi
__device__ unsigned short g_wl[(size_t)NTOK * NHID];  // Wd fp16 lo
__device__ unsigned short g_xh[(size_t)T * B * NHID]; // activations fp16 hi
__device__ unsigned short g_xl[(size_t)T * B * NHID]; // activations fp16 lo
__device__ unsigned short g_wihh[(size_t)NLAYERS * NB * 4 * BS * NINP]; // Wih hi
__device__ unsigned short g_wihl[(size_t)NLAYERS * NB * 4 * BS * NINP]; // Wih lo

// ---------------- f32x2 helpers ---------------------------------------------
__device__ __forceinline__ unsigned long long splat2(float a) {
    unsigned long long r;
    unsigned int u = __float_as_uint(a);
    asm("mov.b64 %0, {%1, %1};" : "=l"(r) : "r"(u));
    return r;
}
__device__ __forceinline__ unsigned long long pack2(float x, float y) {
    unsigned long long r;
    asm("mov.b64 %0, {%1, %2};" : "=l"(r)
        : "r"(__float_as_uint(x)), "r"(__float_as_uint(y)));
    return r;
}
__device__ __forceinline__ void ffma2(unsigned long long &c, unsigned long long a,
                                      unsigned long long b) {
    asm("fma.rn.f32x2 %0, %1, %2, %0;" : "+l"(c) : "l"(a), "l"(b));
}
__device__ __forceinline__ float2 unpk(unsigned long long v) {
    unsigned int x, y;
    asm("mov.b64 {%0, %1}, %2;" : "=r"(x), "=r"(y) : "l"(v));
    return make_float2(__uint_as_float(x), __uint_as_float(y));
}
__device__ __forceinline__ float sigmoidf_(float x) { return 1.f / (1.f + expf(-x)); }

// ---------------- fp32 -> (hi, lo) fp16 split precompute ---------------------
__global__ void k_cvt(const float4* __restrict__ src,
                      unsigned short* __restrict__ hi,
                      unsigned short* __restrict__ lo) {
    size_t idx = (size_t)blockIdx.x * blockDim.x + threadIdx.x;
    float4 v = src[idx];
    float f[4] = {v.x, v.y, v.z, v.w};
    __half h[4], l[4];
#pragma unroll
    for (int i = 0; i < 4; ++i) {
        h[i] = __float2half_rn(f[i]);
        l[i] = __float2half_rn(f[i] - __half2float(h[i]));
    }
    uint2 hp, lp;
    hp.x = ((uint32_t)*(unsigned short*)&h[1] << 16) | *(unsigned short*)&h[0];
    hp.y = ((uint32_t)*(unsigned short*)&h[3] << 16) | *(unsigned short*)&h[2];
    lp.x = ((uint32_t)*(unsigned short*)&l[1] << 16) | *(unsigned short*)&l[0];
    lp.y = ((uint32_t)*(unsigned short*)&l[3] << 16) | *(unsigned short*)&l[2];
    *(uint2*)(hi + idx * 4) = hp;
    *(uint2*)(lo + idx * 4) = lp;
}

// ---------------- HMMA fp16 + ldmatrix + cp.async helpers --------------------
__device__ __forceinline__ void mma16816(float* d, uint32_t a0, uint32_t a1,
                                         uint32_t a2, uint32_t a3,
                                         uint32_t b0, uint32_t b1) {
    asm volatile(
        "mma.sync.aligned.m16n8k16.row.col.f32.f16.f16.f32 "
        "{%0,%1,%2,%3},{%4,%5,%6,%7},{%8,%9},{%0,%1,%2,%3};"
        : "+f"(d[0]), "+f"(d[1]), "+f"(d[2]), "+f"(d[3])
        : "r"(a0), "r"(a1), "r"(a2), "r"(a3), "r"(b0), "r"(b1));
}
__device__ __forceinline__ uint32_t smem_u32(const void* p) {
    uint32_t a;
    asm("{ .reg .u64 t; cvta.to.shared.u64 t, %1; cvt.u32.u64 %0, t; }"
        : "=r"(a) : "l"(p));
    return a;
}
__device__ __forceinline__ void ldsm4(uint32_t &r0, uint32_t &r1, uint32_t &r2,
                                      uint32_t &r3, uint32_t addr) {
    asm volatile("ldmatrix.sync.aligned.m8n8.x4.shared.b16 {%0,%1,%2,%3},[%4];"
                 : "=r"(r0), "=r"(r1), "=r"(r2), "=r"(r3) : "r"(addr));
}
__device__ __forceinline__ void ldsm2(uint32_t &r0, uint32_t &r1, uint32_t addr) {
    asm volatile("ldmatrix.sync.aligned.m8n8.x2.shared.b16 {%0,%1},[%2];"
                 : "=r"(r0), "=r"(r1) : "r"(addr));
}
__device__ __forceinline__ void cpasync16(uint32_t dst, const void* src) {
    asm volatile("cp.async.cg.shared.global [%0], [%1], 16;"
                 :: "r"(dst), "l"(src) : "memory");
}
#define CP_COMMIT() asm volatile("cp.async.commit_group;" ::: "memory")
#define CP_WAIT1() asm volatile("cp.async.wait_group 1;" ::: "memory")
#define CP_WAIT0() asm volatile("cp.async.wait_group 0;" ::: "memory")

// ---------------- tensor-core GEMM (fp16 3-term, cp.async pipeline) ----------
// CTA 128x128, 8 warps (64x32 warp tile), K-chunk 32, double-buffered smem.
#define DEC_SMEM (2 * 40960)
__global__ void __launch_bounds__(256, 2) k_mma(
    const unsigned short* __restrict__ Xh, const unsigned short* __restrict__ Xl,
    const unsigned short* __restrict__ Wh, const unsigned short* __restrict__ Wl,
    const float* __restrict__ bias, float* __restrict__ out, int ldc) {
    extern __shared__ char sm[];
    const uint32_t sbase = smem_u32(sm);
    const int tid = threadIdx.x;
    const int wid = tid >> 5, lid = tid & 31;
    const int m0 = blockIdx.x * 128;
    const int n0 = blockIdx.y * 128;
    const int warpM = wid >> 2;
    const int warpN = wid & 3;
    const int laneR = lid >> 2;
    const int laneC2 = (lid & 3) * 2;
    const uint32_t aoff = (uint32_t)((lid & 15) * 80 + (lid >> 4) * 16);
    const uint32_t boff = (uint32_t)((lid & 7) * 80 + ((lid >> 3) & 1) * 16);

    const int lrow = tid >> 1;
    const int lseg = tid & 1;
    const unsigned short* arh = Xh + (size_t)(m0 + lrow) * 1024 + lseg * 16;
    const unsigned short* arl = Xl + (size_t)(m0 + lrow) * 1024 + lseg * 16;
    const unsigned short* brh = Wh + (size_t)(n0 + lrow) * 1024 + lseg * 16;
    const unsigned short* brl = Wl + (size_t)(n0 + lrow) * 1024 + lseg * 16;
    const uint32_t sdst = sbase + (uint32_t)(lrow * 80 + lseg * 32);

    float acc[4][4][4];
#pragma unroll
    for (int a = 0; a < 4; ++a)
#pragma unroll
        for (int b = 0; b < 4; ++b)
#pragma unroll
            for (int c = 0; c < 4; ++c) acc[a][b][c] = 0.f;

    auto issue = [&](int kc, int b) {
        uint32_t base = sdst + (uint32_t)b * 40960u;
        int koff = kc * 32;
        cpasync16(base, arh + koff);
        cpasync16(base + 16, arh + koff + 8);
        cpasync16(base + 10240, arl + koff);
        cpasync16(base + 10240 + 16, arl + koff + 8);
        cpasync16(base + 20480, brh + koff);
        cpasync16(base + 20480 + 16, brh + koff + 8);
        cpasync16(base + 30720, brl + koff);
        cpasync16(base + 30720 + 16, brl + koff + 8);
        CP_COMMIT();
    };
    issue(0, 0);
    issue(1, 1);

    const int NCH = 1024 / 32;
    for (int kc = 0; kc < NCH; ++kc) {
        if (kc < NCH - 1) { CP_WAIT1(); } else { CP_WAIT0(); }
        __syncthreads();
        const uint32_t bufoff = (uint32_t)(kc & 1) * 40960u;
#pragma unroll
        for (int ks = 0; ks < 2; ++ks) {
            uint32_t ah[4][4], al[4][4], bh[4][2], bl[4][2];
#pragma unroll
            for (int mt = 0; mt < 4; ++mt) {
                uint32_t ad = sbase + bufoff +
                              (uint32_t)((warpM * 64 + mt * 16) * 80 + ks * 32) + aoff;
                ldsm4(ah[mt][0], ah[mt][1], ah[mt][2], ah[mt][3], ad);
                ldsm4(al[mt][0], al[mt][1], al[mt][2], al[mt][3], ad + 10240);
            }
#pragma unroll
            for (int nt = 0; nt < 4; ++nt) {
                uint32_t bd_ = sbase + bufoff + 20480u +
                               (uint32_t)((warpN * 32 + nt * 8) * 80 + ks * 32) + boff;
                ldsm2(bh[nt][0], bh[nt][1], bd_);
                ldsm2(bl[nt][0], bl[nt][1], bd_ + 10240);
            }
#pragma unroll
            for (int mt = 0; mt < 4; ++mt)
#pragma unroll
                for (int nt = 0; nt < 4; ++nt)
                    mma16816(acc[mt][nt], ah[mt][0], ah[mt][1], ah[mt][2], ah[mt][3],
                             bh[nt][0], bh[nt][1]);
#pragma unroll
            for (int mt = 0; mt < 4; ++mt)
#pragma unroll
                for (int nt = 0; nt < 4; ++nt)
                    mma16816(acc[mt][nt], ah[mt][0], ah[mt][1], ah[mt][2], ah[mt][3],
                             bl[nt][0], bl[nt][1]);
#pragma unroll
            for (int mt = 0; mt < 4; ++mt)
#pragma unroll
                for (int nt = 0; nt < 4; ++nt)
                    mma16816(acc[mt][nt], al[mt][0], al[mt][1], al[mt][2], al[mt][3],
                             bh[nt][0], bh[nt][1]);
        }
        __syncthreads();
        if (kc + 2 < NCH) issue(kc + 2, kc & 1);
    }

#pragma unroll
    for (int mt = 0; mt < 4; ++mt) {
        int m = m0 + warpM * 64 + mt * 16 + laneR;
#pragma unroll
        for (int nt = 0; nt < 4; ++nt) {
            int n = n0 + warpN * 32 + nt * 8 + laneC2;
            float bx = 0.f, by = 0.f;
            if (bias) { bx = bias[n]; by = bias[n + 1]; }
            *(float2*)(out + (size_t)m * ldc + n) =
                make_float2(acc[mt][nt][0] + bx, acc[mt][nt][1] + by);
            *(float2*)(out + (size_t)(m + 8) * ldc + n) =
                make_float2(acc[mt][nt][2] + bx, acc[mt][nt][3] + by);
        }
    }
}

// ---------------- embedding gather ------------------------------------------
__global__ void k_embed(const int* __restrict__ tokens, const float* __restrict__ embW,
                        float* __restrict__ x) {
    int tb = blockIdx.x;
    int tok = tokens[tb];
    const float4* src = (const float4*)(embW + (size_t)tok * NINP);
    float4* dst = (float4*)(x + (size_t)tb * NINP);
    dst[threadIdx.x] = src[threadIdx.x];
}

// ---------------- hierarchical epoch grid barrier ----------------------------
// CTA0 aggregates per-CTA flags, releases one epoch line; others poll epoch
// with one thread + nanosleep backoff. Kills the 16K-thread poll storm.
__device__ __forceinline__ void gbar(unsigned &gen) {
    __syncthreads();
    ++gen;
    if (threadIdx.x == 0) {
        asm volatile("st.release.gpu.global.u32 [%0], %1;"
                     :: "l"(&g_flags[blockIdx.x * 32]), "r"(gen) : "memory");
    }
    if (blockIdx.x == 0) {
        if (threadIdx.x < NCTA) {
            unsigned v;
            do {
                asm volatile("ld.acquire.gpu.global.u32 %0, [%1];"
                             : "=r"(v) : "l"(&g_flags[threadIdx.x * 32]) : "memory");
                if (v < gen) __nanosleep(32);
            } while (v < gen);
        }
        __syncthreads();
        if (threadIdx.x == 0) {
            asm volatile("st.release.gpu.global.u32 [%0], %1;"
                         :: "l"(&g_epoch[0]), "r"(gen) : "memory");
        }
    } else {
        if (threadIdx.x == 0) {
            unsigned v;
            do {
                asm volatile("ld.acquire.gpu.global.u32 %0, [%1];"
                             : "=r"(v) : "l"(&g_epoch[0]) : "memory");
                if (v < gen) __nanosleep(32);
            } while (v < gen);
        }
        __syncthreads();
    }
}

// ---------------- persistent recurrence kernel v3 (one layer) ----------------
#define SMEM_REC (43008 * 4)
__global__ void __launch_bounds__(256, 1) k_rec(
    const float* __restrict__ xg, const float* __restrict__ Whh_l,
    const float* __restrict__ bih_l, const float* __restrict__ bhh_l,
    const float* __restrict__ h0_l, const float* __restrict__ c0_l,
    const float* __restrict__ wq, const float* __restrict__ bq,
    const float* __restrict__ wk, const float* __restrict__ bk,
    const float* __restrict__ wv, const float* __restrict__ bv,
    const float* __restrict__ wfc, const float* __restrict__ bfc,
    const float* __restrict__ lng, const float* __restrict__ lnb,
    float* __restrict__ hbuf, float* __restrict__ hlbuf,
    float* __restrict__ ys,
    float* __restrict__ outH, float* __restrict__ outC) {
    extern __shared__ float smf[];
    float* swf  = smf;            // Whh slice [256 k][36 cols]
    float* sa2  = smf + 9216;     // h tile [64 bb][260] (MHA aliases)
    float* smw  = smf + 25856;    // q/k/v weights [48][256]
    float* swfc = smf + 38144;    // wfc [256][16]
    float* sbfc = smf + 42240;
    float* slng = smf + 42496;
    float* slnb = smf + 42752;

    __shared__ float sq2[2][DK], skk2[2][NB][DK], svv2[2][NB][DK];
    __shared__ float ssc2[2][NB], sp2[2][NB], so2[2][DK], sredh[2][4];

    const int tid = threadIdx.x;
    const int r = blockIdx.x;
    const int n = r & 3;
    const int j0 = (r >> 2) * 8;
    const int tj = tid & 7, tb2 = tid >> 3;
    const int j = j0 + tj;
    const int lane = tid & 31;

    {
        const float* W = Whh_l + (size_t)n * 4 * BS * BS;
#pragma unroll
        for (int e = 0; e < 8; ++e) {
            int idx = e * 256 + tid;
            int col = idx >> 6, kq = idx & 63;
            int g = col & 3, jj = col >> 2;
            float4 v = *(const float4*)(W + (size_t)(g * BS + j0 + jj) * BS + kq * 4);
            swf[(kq * 4 + 0) * 36 + col] = v.x;
            swf[(kq * 4 + 1) * 36 + col] = v.y;
            swf[(kq * 4 + 2) * 36 + col] = v.z;
            swf[(kq * 4 + 3) * 36 + col] = v.w;
        }
#pragma unroll
        for (int i = 0; i < 4; ++i) {
            ((float4*)smw)[tid + i * 256] = ((const float4*)wq)[tid + i * 256];
            ((float4*)(smw + 4096))[tid + i * 256] = ((const float4*)wk)[tid + i * 256];
            ((float4*)(smw + 8192))[tid + i * 256] = ((const float4*)wv)[tid + i * 256];
            ((float4*)swfc)[tid + i * 256] = ((const float4*)wfc)[tid + i * 256];
        }
        sbfc[tid] = bfc[tid];
        slng[tid] = lng[tid];
        slnb[tid] = lnb[tid];
    }

    const float b_i = bih_l[n * 4 * BS + 0 * BS + j] + bhh_l[n * 4 * BS + 0 * BS + j];
    const float b_f = bih_l[n * 4 * BS + 1 * BS + j] + bhh_l[n * 4 * BS + 1 * BS + j];
    const float b_g = bih_l[n * 4 * BS + 2 * BS + j] + bhh_l[n * 4 * BS + 2 * BS + j];
    const float b_o = bih_l[n * 4 * BS + 3 * BS + j] + bhh_l[n * 4 * BS + 3 * BS + j];
    float creg[2];
    creg[0] = c0_l[(tb2 * 2 + 0) * NHID + n * BS + j];
    creg[1] = c0_l[(tb2 * 2 + 1) * NHID + n * BS + j];

    unsigned bgen = g_flags[r * 32];

    {
        int base = (r * 256 + tid) * 2;
        float2 v = *(const float2*)(h0_l + base);
        __stcg((float2*)(hbuf + base), v);
    }

    float xgv[2][4];
    {
        const float* xg_t = xg;
#pragma unroll
        for (int bi = 0; bi < 2; ++bi) {
            const float* xr = xg_t + (size_t)(tb2 * 2 + bi) * 4096 + n * 1024 + j;
            xgv[bi][0] = __ldg(xr);       xgv[bi][1] = __ldg(xr + 256);
            xgv[bi][2] = __ldg(xr + 512); xgv[bi][3] = __ldg(xr + 768);
        }
    }
    gbar(bgen);

    const int htid = tid & 127;
    const int half = tid >> 7;
    const int item = r + half * 128;
    const int nn2 = item >> 6;
    const int bb2 = item & 63;
    float* sh = sa2 + half * 1088;
#define HBAR() asm volatile("bar.sync %0, 128;" :: "r"(half + 1) : "memory")

    for (int t = 0; t < T; ++t) {
#pragma unroll 4
        for (int i = 0; i < 16; ++i) {
            int idx = tid + i * 256;
            int bb = idx >> 6, kq = idx & 63;
            float4 v = __ldcg((const float4*)(hbuf + (size_t)bb * NHID + n * BS) + kq);
            *(float4*)&sa2[bb * 260 + kq * 4] = v;
        }
        __syncthreads();

        unsigned long long a00 = pack2(xgv[0][0] + b_i, xgv[0][1] + b_f);
        unsigned long long a01 = pack2(xgv[0][2] + b_g, xgv[0][3] + b_o);
        unsigned long long a10 = pack2(xgv[1][0] + b_i, xgv[1][1] + b_f);
        unsigned long long a11 = pack2(xgv[1][2] + b_g, xgv[1][3] + b_o);
        const float* s0 = &sa2[(tb2 * 2 + 0) * 260];
        const float* s1 = &sa2[(tb2 * 2 + 1) * 260];
        const float* wrow = &swf[tj * 4];
#pragma unroll 8
        for (int k = 0; k < 256; ++k) {
            ulonglong2 wv = *(const ulonglong2*)(wrow + k * 36);
            unsigned long long as0 = splat2(s0[k]);
            unsigned long long as1 = splat2(s1[k]);
            ffma2(a00, as0, wv.x); ffma2(a01, as0, wv.y);
            ffma2(a10, as1, wv.x); ffma2(a11, as1, wv.y);
        }
        {
            float2 g01 = unpk(a00), g23 = unpk(a01);
            float cn = sigmoidf_(g01.y) * creg[0] + sigmoidf_(g01.x) * tanhf(g23.x);
            creg[0] = cn;
            __stcg(hlbuf + (tb2 * 2 + 0) * NHID + n * BS + j,
                   sigmoidf_(g23.y) * tanhf(cn));
            g01 = unpk(a10); g23 = unpk(a11);
            cn = sigmoidf_(g01.y) * creg[1] + sigmoidf_(g01.x) * tanhf(g23.x);
            creg[1] = cn;
            __stcg(hlbuf + (tb2 * 2 + 1) * NHID + n * BS + j,
                   sigmoidf_(g23.y) * tanhf(cn));
        }
        gbar(bgen);

        float* ys_t = ys + (size_t)t * B * NHID;
        {
            const float4* src = (const float4*)(hlbuf + (size_t)bb2 * NHID);
            ((float4*)sh)[htid] = __ldcg(src + htid);
            ((float4*)sh)[htid + 128] = __ldcg(src + htid + 128);
        }
        HBAR();
        for (int w = htid; w < 144; w += 128) {
            const float *hv, *wr; float* dst; float bpv;
            if (w < 16) { wr = smw + w * 256; hv = sh + nn2 * 256;
                          dst = &sq2[half][w]; bpv = __ldg(bq + w); }
            else if (w < 80) { int m = (w - 16) >> 4, d = (w - 16) & 15;
                               wr = smw + 4096 + d * 256; hv = sh + m * 256;
                               dst = &skk2[half][m][d]; bpv = __ldg(bk + d); }
            else { int m = (w - 80) >> 4, d = (w - 80) & 15;
                   wr = smw + 8192 + d * 256; hv = sh + m * 256;
                   dst = &svv2[half][m][d]; bpv = __ldg(bv + d); }
            float a0 = 0, a1 = 0, a2 = 0, a3 = 0;
#pragma unroll 8
            for (int jj = 0; jj < 256; jj += 4) {
                a0 += hv[jj] * wr[jj];         a1 += hv[jj + 1] * wr[jj + 1];
                a2 += hv[jj + 2] * wr[jj + 2]; a3 += hv[jj + 3] * wr[jj + 3];
            }
            *dst = a0 + a1 + a2 + a3 + bpv;
        }
        HBAR();
        if (htid < 4) {
            float s = 0;
#pragma unroll
            for (int d = 0; d < DK; ++d) s += sq2[half][d] * skk2[half][htid][d];
            ssc2[half][htid] = s * 0.25f;
        }
        HBAR();
        if (htid < 4) {
            float mx = fmaxf(fmaxf(ssc2[half][0], ssc2[half][1]),
                             fmaxf(ssc2[half][2], ssc2[half][3]));
            float sum = expf(ssc2[half][0] - mx) + expf(ssc2[half][1] - mx) +
                        expf(ssc2[half][2] - mx) + expf(ssc2[half][3] - mx);
            sp2[half][htid] = expf(ssc2[half][htid] - mx) / sum;
        }
        HBAR();
        if (htid < DK) {
            float o = 0;
#pragma unroll
            for (int m = 0; m < NB; ++m) o += sp2[half][m] * svv2[half][m][htid];
            so2[half][htid] = o;
        }
        HBAR();
        float v0 = sbfc[htid] + sh[nn2 * 256 + htid];
        float v1 = sbfc[htid + 128] + sh[nn2 * 256 + htid + 128];
#pragma unroll
        for (int d = 0; d < DK; ++d) {
            v0 += so2[half][d] * swfc[htid * DK + d];
            v1 += so2[half][d] * swfc[(htid + 128) * DK + d];
        }
        float s = v0 + v1;
#pragma unroll
        for (int off = 16; off; off >>= 1) s += __shfl_down_sync(0xffffffffu, s, off);
        if (lane == 0) sredh[half][htid >> 5] = s;
        HBAR();
        float mu = (sredh[half][0] + sredh[half][1] + sredh[half][2] + sredh[half][3])
                   * (1.f / BS);
        HBAR();
        float dv0 = v0 - mu, dv1 = v1 - mu;
        float s2 = dv0 * dv0 + dv1 * dv1;
#pragma unroll
        for (int off = 16; off; off >>= 1) s2 += __shfl_down_sync(0xffffffffu, s2, off);
        if (lane == 0) sredh[half][htid >> 5] = s2;
        HBAR();
        float var = (sredh[half][0] + sredh[half][1] + sredh[half][2] + sredh[half][3])
                    * (1.f / BS);
        float rstd = rsqrtf(var + 1e-5f);
        float y0 = dv0 * rstd * slng[htid] + slnb[htid];
        float y1 = dv1 * rstd * slng[htid + 128] + slnb[htid + 128];
        int i0 = bb2 * NHID + nn2 * 256 + htid;
        __stcg(hbuf + i0, y0);       ys_t[i0] = y0;
        __stcg(hbuf + i0 + 128, y1); ys_t[i0 + 128] = y1;

        if (t + 1 < T) {
            const float* xg_t = xg + (size_t)(t + 1) * B * 4096;
#pragma unroll
            for (int bi = 0; bi < 2; ++bi) {
                const float* xr = xg_t + (size_t)(tb2 * 2 + bi) * 4096 + n * 1024 + j;
                xgv[bi][0] = __ldg(xr);       xgv[bi][1] = __ldg(xr + 256);
                xgv[bi][2] = __ldg(xr + 512); xgv[bi][3] = __ldg(xr + 768);
            }
        }
        gbar(bgen);
    }

    {
        int base = (r * 256 + tid) * 2;
        float2 v = __ldcg((const float2*)(hbuf + base));
        *(float2*)(outH + base) = v;
    }
    outC[(tb2 * 2 + 0) * NHID + n * BS + j] = creg[0];
    outC[(tb2 * 2 + 1) * NHID + n * BS + j] = creg[1];
#undef HBAR
}

// ---------------- host driver ------------------------------------------------
extern "C" void kernel_launch(void* const* d_in, const int* in_sizes, int n_in,
                              void* d_out, int out_size) {
    const int* tokens = (const int*)d_in[0];
    const float* h0 = (const float*)d_in[1];
    const float* c0 = (const float*)d_in[2];
    const float* embW = (const float*)d_in[3];
    const float* Wih = (const float*)d_in[4];
    const float* Whh = (const float*)d_in[5];
    const float* bih = (const float*)d_in[6];
    const float* bhh = (const float*)d_in[7];
    const float* wq = (const float*)d_in[8];
    const float* bq = (const float*)d_in[9];
    const float* wk = (const float*)d_in[10];
    const float* bk = (const float*)d_in[11];
    const float* wv = (const float*)d_in[12];
    const float* bv = (const float*)d_in[13];
    const float* wfc = (const float*)d_in[14];
    const float* bfc = (const float*)d_in[15];
    const float* lng = (const float*)d_in[16];
    const float* lnb = (const float*)d_in[17];
    const float* Wd = (const float*)d_in[18];
    const float* bd = (const float*)d_in[19];
    float* out = (float*)d_out;

    static int attr_set = 0;
    if (!attr_set) {
        cudaFuncSetAttribute(k_rec, cudaFuncAttributeMaxDynamicSharedMemorySize,
                             SMEM_REC);
        cudaFuncSetAttribute(k_mma, cudaFuncAttributeMaxDynamicSharedMemorySize,
                             DEC_SMEM);
        attr_set = 1;
    }

    float *xb, *xg, *hbuf, *hlbuf;
    unsigned short *wh, *wl, *xh, *xl, *wihh, *wihl;
    cudaGetSymbolAddress((void**)&xb, g_xbuf);
    cudaGetSymbolAddress((void**)&xg, g_xg);
    cudaGetSymbolAddress((void**)&hbuf, g_h);
    cudaGetSymbolAddress((void**)&hlbuf, g_hl);
    cudaGetSymbolAddress((void**)&wh, g_wh);
    cudaGetSymbolAddress((void**)&wl, g_wl);
    cudaGetSymbolAddress((void**)&xh, g_xh);
    cudaGetSymbolAddress((void**)&xl, g_xl);
    cudaGetSymbolAddress((void**)&wihh, g_wihh);
    cudaGetSymbolAddress((void**)&wihl, g_wihl);
    float* x0 = xb;
    float* x1 = xb + (size_t)T * B * NHID;

    // weight conversions (fp16 hi/lo planes)
    k_cvt<<<(int)(((size_t)NTOK * NHID / 4) / 256), 256>>>((const float4*)Wd, wh, wl);
    k_cvt<<<(int)(((size_t)NLAYERS * NB * 4 * BS * NINP / 4) / 256), 256>>>(
        (const float4*)Wih, wihh, wihl);

    k_embed<<<T * B, 256>>>(tokens, embW, x0);

    const size_t DECN = (size_t)T * B * NTOK;
    const size_t WIH_L = (size_t)NB * 4 * BS * NINP;
    for (int l = 0; l < NLAYERS; ++l) {
        const float* xin = (l == 0) ? x0 : x1;
        float* xout = (l == 0) ? x1 : x0;
        const float* Whh_l = Whh + (size_t)l * NB * 4 * BS * BS;
        const float* bih_l = bih + (size_t)l * NB * 4 * BS;
        const float* bhh_l = bhh + (size_t)l * NB * 4 * BS;
        // xg = xin @ Wih_l^T on tensor cores (fp16 3-term)
        k_cvt<<<(int)(((size_t)T * B * NHID / 4) / 256), 256>>>(
            (const float4*)xin, xh, xl);
        k_mma<<<dim3(32, 32), 256, DEC_SMEM>>>(xh, xl, wihh + l * WIH_L,
                                               wihl + l * WIH_L, nullptr, xg,
                                               NB * 4 * BS);
        k_rec<<<NCTA, 256, SMEM_REC>>>(xg, Whh_l, bih_l, bhh_l,
                                       h0 + (size_t)l * B * NHID,
                                       c0 + (size_t)l * B * NHID,
                                       wq, bq, wk, bk, wv, bv, wfc, bfc, lng, lnb,
                                       hbuf, hlbuf, xout,
                                       out + DECN + (size_t)l * B * NHID,
                                       out + DECN + (size_t)NLAYERS * B * NHID +
                                           (size_t)l * B * NHID);
    }
    // decoder: out = x0 @ Wd^T + bd (fp16 3-term)
    k_cvt<<<(int)(((size_t)T * B * NHID / 4) / 256), 256>>>((const float4*)x0, xh, xl);
    k_mma<<<dim3(32, 250), 256, DEC_SMEM>>>(xh, xl, wh, wl, bd, out, NTOK);
}

// round 12
// speedup vs baseline: 1.0376x; 1.0376x over previous
#include <cuda_runtime.h>
#include <cuda_fp16.h>
#include <cstdint>

#define NLAYERS 2
#define NB 4
#define BS 256
#define NHID 1024
#define NINP 1024
#define NTOK 32000
#define T 64
#define B 64
#define DK 16
#define NCTA 128

// ---------------- scratch (device globals: no allocation allowed) ----------
__device__ float g_xbuf[2][(size_t)T * B * NHID];
__device__ float g_xg[(size_t)T * B * NB * 4 * BS];
__device__ float g_h[B * NHID];
__device__ float g_hl[B * NHID];
__device__ unsigned g_flags[NCTA * 32];               // one flag per 128B line
__device__ unsigned short g_wh[(size_t)NTOK * NHID];  // Wd fp16 hi
__device__ unsigned short g_wl[(size_t)NTOK * NHID];  // Wd fp16 lo
__device__ unsigned short g_xh[(size_t)T * B * NHID]; // activations fp16 hi
__device__ unsigned short g_xl[(size_t)T * B * NHID]; // activations fp16 lo
__device__ unsigned short g_wihh[(size_t)NLAYERS * NB * 4 * BS * NINP]; // Wih hi
__device__ unsigned short g_wihl[(size_t)NLAYERS * NB * 4 * BS * NINP]; // Wih lo

// ---------------- f32x2 helpers ---------------------------------------------
__device__ __forceinline__ unsigned long long splat2(float a) {
    unsigned long long r;
    unsigned int u = __float_as_uint(a);
    asm("mov.b64 %0, {%1, %1};" : "=l"(r) : "r"(u));
    return r;
}
__device__ __forceinline__ unsigned long long pack2(float x, float y) {
    unsigned long long r;
    asm("mov.b64 %0, {%1, %2};" : "=l"(r)
        : "r"(__float_as_uint(x)), "r"(__float_as_uint(y)));
    return r;
}
__device__ __forceinline__ void ffma2(unsigned long long &c, unsigned long long a,
                                      unsigned long long b) {
    asm("fma.rn.f32x2 %0, %1, %2, %0;" : "+l"(c) : "l"(a), "l"(b));
}
__device__ __forceinline__ float2 unpk(unsigned long long v) {
    unsigned int x, y;
    asm("mov.b64 {%0, %1}, %2;" : "=r"(x), "=r"(y) : "l"(v));
    return make_float2(__uint_as_float(x), __uint_as_float(y));
}
__device__ __forceinline__ float sigmoidf_(float x) { return 1.f / (1.f + expf(-x)); }

// ---------------- fp32 -> (hi, lo) fp16 split precompute ---------------------
__global__ void k_cvt(const float4* __restrict__ src,
                      unsigned short* __restrict__ hi,
                      unsigned short* __restrict__ lo) {
    size_t idx = (size_t)blockIdx.x * blockDim.x + threadIdx.x;
    float4 v = src[idx];
    float f[4] = {v.x, v.y, v.z, v.w};
    __half h[4], l[4];
#pragma unroll
    for (int i = 0; i < 4; ++i) {
        h[i] = __float2half_rn(f[i]);
        l[i] = __float2half_rn(f[i] - __half2float(h[i]));
    }
    uint2 hp, lp;
    hp.x = ((uint32_t)*(unsigned short*)&h[1] << 16) | *(unsigned short*)&h[0];
    hp.y = ((uint32_t)*(unsigned short*)&h[3] << 16) | *(unsigned short*)&h[2];
    lp.x = ((uint32_t)*(unsigned short*)&l[1] << 16) | *(unsigned short*)&l[0];
    lp.y = ((uint32_t)*(unsigned short*)&l[3] << 16) | *(unsigned short*)&l[2];
    *(uint2*)(hi + idx * 4) = hp;
    *(uint2*)(lo + idx * 4) = lp;
}

// ---------------- HMMA fp16 + ldmatrix + cp.async helpers --------------------
__device__ __forceinline__ void mma16816(float* d, uint32_t a0, uint32_t a1,
                                         uint32_t a2, uint32_t a3,
                                         uint32_t b0, uint32_t b1) {
    asm volatile(
        "mma.sync.aligned.m16n8k16.row.col.f32.f16.f16.f32 "
        "{%0,%1,%2,%3},{%4,%5,%6,%7},{%8,%9},{%0,%1,%2,%3};"
        : "+f"(d[0]), "+f"(d[1]), "+f"(d[2]), "+f"(d[3])
        : "r"(a0), "r"(a1), "r"(a2), "r"(a3), "r"(b0), "r"(b1));
}
__device__ __forceinline__ uint32_t smem_u32(const void* p) {
    uint32_t a;
    asm("{ .reg .u64 t; cvta.to.shared.u64 t, %1; cvt.u32.u64 %0, t; }"
        : "=r"(a) : "l"(p));
    return a;
}
__device__ __forceinline__ void ldsm4(uint32_t &r0, uint32_t &r1, uint32_t &r2,
                                      uint32_t &r3, uint32_t addr) {
    asm volatile("ldmatrix.sync.aligned.m8n8.x4.shared.b16 {%0,%1,%2,%3},[%4];"
                 : "=r"(r0), "=r"(r1), "=r"(r2), "=r"(r3) : "r"(addr));
}
__device__ __forceinline__ void ldsm2(uint32_t &r0, uint32_t &r1, uint32_t addr) {
    asm volatile("ldmatrix.sync.aligned.m8n8.x2.shared.b16 {%0,%1},[%2];"
                 : "=r"(r0), "=r"(r1) : "r"(addr));
}
__device__ __forceinline__ void cpasync16(uint32_t dst, const void* src) {
    asm volatile("cp.async.cg.shared.global [%0], [%1], 16;"
                 :: "r"(dst), "l"(src) : "memory");
}
#define CP_COMMIT() asm volatile("cp.async.commit_group;" ::: "memory")
#define CP_WAIT1() asm volatile("cp.async.wait_group 1;" ::: "memory")
#define CP_WAIT0() asm volatile("cp.async.wait_group 0;" ::: "memory")

// ---------------- tensor-core GEMM (fp16 3-term, cp.async pipeline) ----------
// CTA 128x128, 8 warps (64x32 warp tile), K-chunk 32, double-buffered smem.
#define DEC_SMEM (2 * 40960)
__global__ void __launch_bounds__(256, 2) k_mma(
    const unsigned short* __restrict__ Xh, const unsigned short* __restrict__ Xl,
    const unsigned short* __restrict__ Wh, const unsigned short* __restrict__ Wl,
    const float* __restrict__ bias, float* __restrict__ out, int ldc) {
    extern __shared__ char sm[];
    const uint32_t sbase = smem_u32(sm);
    const int tid = threadIdx.x;
    const int wid = tid >> 5, lid = tid & 31;
    const int m0 = blockIdx.x * 128;
    const int n0 = blockIdx.y * 128;
    const int warpM = wid >> 2;
    const int warpN = wid & 3;
    const int laneR = lid >> 2;
    const int laneC2 = (lid & 3) * 2;
    const uint32_t aoff = (uint32_t)((lid & 15) * 80 + (lid >> 4) * 16);
    const uint32_t boff = (uint32_t)((lid & 7) * 80 + ((lid >> 3) & 1) * 16);

    const int lrow = tid >> 1;
    const int lseg = tid & 1;
    const unsigned short* arh = Xh + (size_t)(m0 + lrow) * 1024 + lseg * 16;
    const unsigned short* arl = Xl + (size_t)(m0 + lrow) * 1024 + lseg * 16;
    const unsigned short* brh = Wh + (size_t)(n0 + lrow) * 1024 + lseg * 16;
    const unsigned short* brl = Wl + (size_t)(n0 + lrow) * 1024 + lseg * 16;
    const uint32_t sdst = sbase + (uint32_t)(lrow * 80 + lseg * 32);

    float acc[4][4][4];
#pragma unroll
    for (int a = 0; a < 4; ++a)
#pragma unroll
        for (int b = 0; b < 4; ++b)
#pragma unroll
            for (int c = 0; c < 4; ++c) acc[a][b][c] = 0.f;

    auto issue = [&](int kc, int b) {
        uint32_t base = sdst + (uint32_t)b * 40960u;
        int koff = kc * 32;
        cpasync16(base, arh + koff);
        cpasync16(base + 16, arh + koff + 8);
        cpasync16(base + 10240, arl + koff);
        cpasync16(base + 10240 + 16, arl + koff + 8);
        cpasync16(base + 20480, brh + koff);
        cpasync16(base + 20480 + 16, brh + koff + 8);
        cpasync16(base + 30720, brl + koff);
        cpasync16(base + 30720 + 16, brl + koff + 8);
        CP_COMMIT();
    };
    issue(0, 0);
    issue(1, 1);

    const int NCH = 1024 / 32;
    for (int kc = 0; kc < NCH; ++kc) {
        if (kc < NCH - 1) { CP_WAIT1(); } else { CP_WAIT0(); }
        __syncthreads();
        const uint32_t bufoff = (uint32_t)(kc & 1) * 40960u;
#pragma unroll
        for (int ks = 0; ks < 2; ++ks) {
            uint32_t ah[4][4], al[4][4], bh[4][2], bl[4][2];
#pragma unroll
            for (int mt = 0; mt < 4; ++mt) {
                uint32_t ad = sbase + bufoff +
                              (uint32_t)((warpM * 64 + mt * 16) * 80 + ks * 32) + aoff;
                ldsm4(ah[mt][0], ah[mt][1], ah[mt][2], ah[mt][3], ad);
                ldsm4(al[mt][0], al[mt][1], al[mt][2], al[mt][3], ad + 10240);
            }
#pragma unroll
            for (int nt = 0; nt < 4; ++nt) {
                uint32_t bd_ = sbase + bufoff + 20480u +
                               (uint32_t)((warpN * 32 + nt * 8) * 80 + ks * 32) + boff;
                ldsm2(bh[nt][0], bh[nt][1], bd_);
                ldsm2(bl[nt][0], bl[nt][1], bd_ + 10240);
            }
#pragma unroll
            for (int mt = 0; mt < 4; ++mt)
#pragma unroll
                for (int nt = 0; nt < 4; ++nt)
                    mma16816(acc[mt][nt], ah[mt][0], ah[mt][1], ah[mt][2], ah[mt][3],
                             bh[nt][0], bh[nt][1]);
#pragma unroll
            for (int mt = 0; mt < 4; ++mt)
#pragma unroll
                for (int nt = 0; nt < 4; ++nt)
                    mma16816(acc[mt][nt], ah[mt][0], ah[mt][1], ah[mt][2], ah[mt][3],
                             bl[nt][0], bl[nt][1]);
#pragma unroll
            for (int mt = 0; mt < 4; ++mt)
#pragma unroll
                for (int nt = 0; nt < 4; ++nt)
                    mma16816(acc[mt][nt], al[mt][0], al[mt][1], al[mt][2], al[mt][3],
                             bh[nt][0], bh[nt][1]);
        }
        __syncthreads();
        if (kc + 2 < NCH) issue(kc + 2, kc & 1);
    }

#pragma unroll
    for (int mt = 0; mt < 4; ++mt) {
        int m = m0 + warpM * 64 + mt * 16 + laneR;
#pragma unroll
        for (int nt = 0; nt < 4; ++nt) {
            int n = n0 + warpN * 32 + nt * 8 + laneC2;
            float bx = 0.f, by = 0.f;
            if (bias) { bx = bias[n]; by = bias[n + 1]; }
            *(float2*)(out + (size_t)m * ldc + n) =
                make_float2(acc[mt][nt][0] + bx, acc[mt][nt][1] + by);
            *(float2*)(out + (size_t)(m + 8) * ldc + n) =
                make_float2(acc[mt][nt][2] + bx, acc[mt][nt][3] + by);
        }
    }
}

// ---------------- embedding gather ------------------------------------------
__global__ void k_embed(const int* __restrict__ tokens, const float* __restrict__ embW,
                        float* __restrict__ x) {
    int tb = blockIdx.x;
    int tok = tokens[tb];
    const float4* src = (const float4*)(embW + (size_t)tok * NINP);
    float4* dst = (float4*)(x + (size_t)tb * NINP);
    dst[threadIdx.x] = src[threadIdx.x];
}

// ---------------- flat padded-flag grid barrier (round-8 design) -------------
__device__ __forceinline__ void gbar(unsigned &gen) {
    __syncthreads();
    ++gen;
    if (threadIdx.x == 0) {
        asm volatile("st.release.gpu.global.u32 [%0], %1;"
                     :: "l"(&g_flags[blockIdx.x * 32]), "r"(gen) : "memory");
    }
    if (threadIdx.x < NCTA) {
        unsigned v;
        do {
            asm volatile("ld.acquire.gpu.global.u32 %0, [%1];"
                         : "=r"(v) : "l"(&g_flags[threadIdx.x * 32]) : "memory");
        } while (v < gen);
    }
    __syncthreads();
}

// ---------------- persistent recurrence kernel v3 (one layer) ----------------
#define SMEM_REC (43008 * 4)
__global__ void __launch_bounds__(256, 1) k_rec(
    const float* __restrict__ xg, const float* __restrict__ Whh_l,
    const float* __restrict__ bih_l, const float* __restrict__ bhh_l,
    const float* __restrict__ h0_l, const float* __restrict__ c0_l,
    const float* __restrict__ wq, const float* __restrict__ bq,
    const float* __restrict__ wk, const float* __restrict__ bk,
    const float* __restrict__ wv, const float* __restrict__ bv,
    const float* __restrict__ wfc, const float* __restrict__ bfc,
    const float* __restrict__ lng, const float* __restrict__ lnb,
    float* __restrict__ hbuf, float* __restrict__ hlbuf,
    float* __restrict__ ys,
    float* __restrict__ outH, float* __restrict__ outC) {
    extern __shared__ float smf[];
    float* swf  = smf;            // Whh slice [256 k][36 cols]
    float* sa2  = smf + 9216;     // h tile [64 bb][260] (MHA aliases)
    float* smw  = smf + 25856;    // q/k/v weights [48][256]
    float* swfc = smf + 38144;    // wfc [256][16]
    float* sbfc = smf + 42240;
    float* slng = smf + 42496;
    float* slnb = smf + 42752;

    __shared__ float sq2[2][DK], skk2[2][NB][DK], svv2[2][NB][DK];
    __shared__ float ssc2[2][NB], sp2[2][NB], so2[2][DK], sredh[2][4];

    const int tid = threadIdx.x;
    const int r = blockIdx.x;
    const int n = r & 3;
    const int j0 = (r >> 2) * 8;
    const int tj = tid & 7, tb2 = tid >> 3;
    const int j = j0 + tj;
    const int lane = tid & 31;

    {
        const float* W = Whh_l + (size_t)n * 4 * BS * BS;
#pragma unroll
        for (int e = 0; e < 8; ++e) {
            int idx = e * 256 + tid;
            int col = idx >> 6, kq = idx & 63;
            int g = col & 3, jj = col >> 2;
            float4 v = *(const float4*)(W + (size_t)(g * BS + j0 + jj) * BS + kq * 4);
            swf[(kq * 4 + 0) * 36 + col] = v.x;
            swf[(kq * 4 + 1) * 36 + col] = v.y;
            swf[(kq * 4 + 2) * 36 + col] = v.z;
            swf[(kq * 4 + 3) * 36 + col] = v.w;
        }
#pragma unroll
        for (int i = 0; i < 4; ++i) {
            ((float4*)smw)[tid + i * 256] = ((const float4*)wq)[tid + i * 256];
            ((float4*)(smw + 4096))[tid + i * 256] = ((const float4*)wk)[tid + i * 256];
            ((float4*)(smw + 8192))[tid + i * 256] = ((const float4*)wv)[tid + i * 256];
            ((float4*)swfc)[tid + i * 256] = ((const float4*)wfc)[tid + i * 256];
        }
        sbfc[tid] = bfc[tid];
        slng[tid] = lng[tid];
        slnb[tid] = lnb[tid];
    }

    const float b_i = bih_l[n * 4 * BS + 0 * BS + j] + bhh_l[n * 4 * BS + 0 * BS + j];
    const float b_f = bih_l[n * 4 * BS + 1 * BS + j] + bhh_l[n * 4 * BS + 1 * BS + j];
    const float b_g = bih_l[n * 4 * BS + 2 * BS + j] + bhh_l[n * 4 * BS + 2 * BS + j];
    const float b_o = bih_l[n * 4 * BS + 3 * BS + j] + bhh_l[n * 4 * BS + 3 * BS + j];
    float creg[2];
    creg[0] = c0_l[(tb2 * 2 + 0) * NHID + n * BS + j];
    creg[1] = c0_l[(tb2 * 2 + 1) * NHID + n * BS + j];

    unsigned bgen = g_flags[r * 32];

    {
        int base = (r * 256 + tid) * 2;
        float2 v = *(const float2*)(h0_l + base);
        __stcg((float2*)(hbuf + base), v);
    }

    float xgv[2][4];
    {
        const float* xg_t = xg;
#pragma unroll
        for (int bi = 0; bi < 2; ++bi) {
            const float* xr = xg_t + (size_t)(tb2 * 2 + bi) * 4096 + n * 1024 + j;
            xgv[bi][0] = __ldg(xr);       xgv[bi][1] = __ldg(xr + 256);
            xgv[bi][2] = __ldg(xr + 512); xgv[bi][3] = __ldg(xr + 768);
        }
    }
    gbar(bgen);

    const int htid = tid & 127;
    const int half = tid >> 7;
    const int item = r + half * 128;
    const int nn2 = item >> 6;
    const int bb2 = item & 63;
    float* sh = sa2 + half * 1088;
#define HBAR() asm volatile("bar.sync %0, 128;" :: "r"(half + 1) : "memory")

    for (int t = 0; t < T; ++t) {
#pragma unroll 4
        for (int i = 0; i < 16; ++i) {
            int idx = tid + i * 256;
            int bb = idx >> 6, kq = idx & 63;
            float4 v = __ldcg((const float4*)(hbuf + (size_t)bb * NHID + n * BS) + kq);
            *(float4*)&sa2[bb * 260 + kq * 4] = v;
        }
        __syncthreads();

        unsigned long long a00 = pack2(xgv[0][0] + b_i, xgv[0][1] + b_f);
        unsigned long long a01 = pack2(xgv[0][2] + b_g, xgv[0][3] + b_o);
        unsigned long long a10 = pack2(xgv[1][0] + b_i, xgv[1][1] + b_f);
        unsigned long long a11 = pack2(xgv[1][2] + b_g, xgv[1][3] + b_o);
        const float* s0 = &sa2[(tb2 * 2 + 0) * 260];
        const float* s1 = &sa2[(tb2 * 2 + 1) * 260];
        const float* wrow = &swf[tj * 4];
#pragma unroll 8
        for (int k = 0; k < 256; ++k) {
            ulonglong2 wv = *(const ulonglong2*)(wrow + k * 36);
            unsigned long long as0 = splat2(s0[k]);
            unsigned long long as1 = splat2(s1[k]);
            ffma2(a00, as0, wv.x); ffma2(a01, as0, wv.y);
            ffma2(a10, as1, wv.x); ffma2(a11, as1, wv.y);
        }
        {
            float2 g01 = unpk(a00), g23 = unpk(a01);
            float cn = sigmoidf_(g01.y) * creg[0] + sigmoidf_(g01.x) * tanhf(g23.x);
            creg[0] = cn;
            __stcg(hlbuf + (tb2 * 2 + 0) * NHID + n * BS + j,
                   sigmoidf_(g23.y) * tanhf(cn));
            g01 = unpk(a10); g23 = unpk(a11);
            cn = sigmoidf_(g01.y) * creg[1] + sigmoidf_(g01.x) * tanhf(g23.x);
            creg[1] = cn;
            __stcg(hlbuf + (tb2 * 2 + 1) * NHID + n * BS + j,
                   sigmoidf_(g23.y) * tanhf(cn));
        }
        gbar(bgen);

        float* ys_t = ys + (size_t)t * B * NHID;
        {
            const float4* src = (const float4*)(hlbuf + (size_t)bb2 * NHID);
            ((float4*)sh)[htid] = __ldcg(src + htid);
            ((float4*)sh)[htid + 128] = __ldcg(src + htid + 128);
        }
        HBAR();
        for (int w = htid; w < 144; w += 128) {
            const float *hv, *wr; float* dst; float bpv;
            if (w < 16) { wr = smw + w * 256; hv = sh + nn2 * 256;
                          dst = &sq2[half][w]; bpv = __ldg(bq + w); }
            else if (w < 80) { int m = (w - 16) >> 4, d = (w - 16) & 15;
                               wr = smw + 4096 + d * 256; hv = sh + m * 256;
                               dst = &skk2[half][m][d]; bpv = __ldg(bk + d); }
            else { int m = (w - 80) >> 4, d = (w - 80) & 15;
                   wr = smw + 8192 + d * 256; hv = sh + m * 256;
                   dst = &svv2[half][m][d]; bpv = __ldg(bv + d); }
            float a0 = 0, a1 = 0, a2 = 0, a3 = 0;
#pragma unroll 8
            for (int jj = 0; jj < 256; jj += 4) {
                a0 += hv[jj] * wr[jj];         a1 += hv[jj + 1] * wr[jj + 1];
                a2 += hv[jj + 2] * wr[jj + 2]; a3 += hv[jj + 3] * wr[jj + 3];
            }
            *dst = a0 + a1 + a2 + a3 + bpv;
        }
        HBAR();
        if (htid < 4) {
            float s = 0;
#pragma unroll
            for (int d = 0; d < DK; ++d) s += sq2[half][d] * skk2[half][htid][d];
            ssc2[half][htid] = s * 0.25f;
        }
        HBAR();
        if (htid < 4) {
            float mx = fmaxf(fmaxf(ssc2[half][0], ssc2[half][1]),
                             fmaxf(ssc2[half][2], ssc2[half][3]));
            float sum = expf(ssc2[half][0] - mx) + expf(ssc2[half][1] - mx) +
                        expf(ssc2[half][2] - mx) + expf(ssc2[half][3] - mx);
            sp2[half][htid] = expf(ssc2[half][htid] - mx) / sum;
        }
        HBAR();
        if (htid < DK) {
            float o = 0;
#pragma unroll
            for (int m = 0; m < NB; ++m) o += sp2[half][m] * svv2[half][m][htid];
            so2[half][htid] = o;
        }
        HBAR();
        float v0 = sbfc[htid] + sh[nn2 * 256 + htid];
        float v1 = sbfc[htid + 128] + sh[nn2 * 256 + htid + 128];
#pragma unroll
        for (int d = 0; d < DK; ++d) {
            v0 += so2[half][d] * swfc[htid * DK + d];
            v1 += so2[half][d] * swfc[(htid + 128) * DK + d];
        }
        float s = v0 + v1;
#pragma unroll
        for (int off = 16; off; off >>= 1) s += __shfl_down_sync(0xffffffffu, s, off);
        if (lane == 0) sredh[half][htid >> 5] = s;
        HBAR();
        float mu = (sredh[half][0] + sredh[half][1] + sredh[half][2] + sredh[half][3])
                   * (1.f / BS);
        HBAR();
        float dv0 = v0 - mu, dv1 = v1 - mu;
        float s2 = dv0 * dv0 + dv1 * dv1;
#pragma unroll
        for (int off = 16; off; off >>= 1) s2 += __shfl_down_sync(0xffffffffu, s2, off);
        if (lane == 0) sredh[half][htid >> 5] = s2;
        HBAR();
        float var = (sredh[half][0] + sredh[half][1] + sredh[half][2] + sredh[half][3])
                    * (1.f / BS);
        float rstd = rsqrtf(var + 1e-5f);
        float y0 = dv0 * rstd * slng[htid] + slnb[htid];
        float y1 = dv1 * rstd * slng[htid + 128] + slnb[htid + 128];
        int i0 = bb2 * NHID + nn2 * 256 + htid;
        __stcg(hbuf + i0, y0);       ys_t[i0] = y0;
        __stcg(hbuf + i0 + 128, y1); ys_t[i0 + 128] = y1;

        if (t + 1 < T) {
            const float* xg_t = xg + (size_t)(t + 1) * B * 4096;
#pragma unroll
            for (int bi = 0; bi < 2; ++bi) {
                const float* xr = xg_t + (size_t)(tb2 * 2 + bi) * 4096 + n * 1024 + j;
                xgv[bi][0] = __ldg(xr);       xgv[bi][1] = __ldg(xr + 256);
                xgv[bi][2] = __ldg(xr + 512); xgv[bi][3] = __ldg(xr + 768);
            }
        }
        gbar(bgen);
    }

    {
        int base = (r * 256 + tid) * 2;
        float2 v = __ldcg((const float2*)(hbuf + base));
        *(float2*)(outH + base) = v;
    }
    outC[(tb2 * 2 + 0) * NHID + n * BS + j] = creg[0];
    outC[(tb2 * 2 + 1) * NHID + n * BS + j] = creg[1];
#undef HBAR
}

// ---------------- host driver ------------------------------------------------
extern "C" void kernel_launch(void* const* d_in, const int* in_sizes, int n_in,
                              void* d_out, int out_size) {
    const int* tokens = (const int*)d_in[0];
    const float* h0 = (const float*)d_in[1];
    const float* c0 = (const float*)d_in[2];
    const float* embW = (const float*)d_in[3];
    const float* Wih = (const float*)d_in[4];
    const float* Whh = (const float*)d_in[5];
    const float* bih = (const float*)d_in[6];
    const float* bhh = (const float*)d_in[7];
    const float* wq = (const float*)d_in[8];
    const float* bq = (const float*)d_in[9];
    const float* wk = (const float*)d_in[10];
    const float* bk = (const float*)d_in[11];
    const float* wv = (const float*)d_in[12];
    const float* bv = (const float*)d_in[13];
    const float* wfc = (const float*)d_in[14];
    const float* bfc = (const float*)d_in[15];
    const float* lng = (const float*)d_in[16];
    const float* lnb = (const float*)d_in[17];
    const float* Wd = (const float*)d_in[18];
    const float* bd = (const float*)d_in[19];
    float* out = (float*)d_out;

    static int attr_set = 0;
    if (!attr_set) {
        cudaFuncSetAttribute(k_rec, cudaFuncAttributeMaxDynamicSharedMemorySize,
                             SMEM_REC);
        cudaFuncSetAttribute(k_mma, cudaFuncAttributeMaxDynamicSharedMemorySize,
                             DEC_SMEM);
        attr_set = 1;
    }

    float *xb, *xg, *hbuf, *hlbuf;
    unsigned short *wh, *wl, *xh, *xl, *wihh, *wihl;
    cudaGetSymbolAddress((void**)&xb, g_xbuf);
    cudaGetSymbolAddress((void**)&xg, g_xg);
    cudaGetSymbolAddress((void**)&hbuf, g_h);
    cudaGetSymbolAddress((void**)&hlbuf, g_hl);
    cudaGetSymbolAddress((void**)&wh, g_wh);
    cudaGetSymbolAddress((void**)&wl, g_wl);
    cudaGetSymbolAddress((void**)&xh, g_xh);
    cudaGetSymbolAddress((void**)&xl, g_xl);
    cudaGetSymbolAddress((void**)&wihh, g_wihh);
    cudaGetSymbolAddress((void**)&wihl, g_wihl);
    float* x0 = xb;
    float* x1 = xb + (size_t)T * B * NHID;

    // weight conversions (fp16 hi/lo planes)
    k_cvt<<<(int)(((size_t)NTOK * NHID / 4) / 256), 256>>>((const float4*)Wd, wh, wl);
    k_cvt<<<(int)(((size_t)NLAYERS * NB * 4 * BS * NINP / 4) / 256), 256>>>(
        (const float4*)Wih, wihh, wihl);

    k_embed<<<T * B, 256>>>(tokens, embW, x0);

    const size_t DECN = (size_t)T * B * NTOK;
    const size_t WIH_L = (size_t)NB * 4 * BS * NINP;
    for (int l = 0; l < NLAYERS; ++l) {
        const float* xin = (l == 0) ? x0 : x1;
        float* xout = (l == 0) ? x1 : x0;
        const float* Whh_l = Whh + (size_t)l * NB * 4 * BS * BS;
        const float* bih_l = bih + (size_t)l * NB * 4 * BS;
        const float* bhh_l = bhh + (size_t)l * NB * 4 * BS;
        // xg = xin @ Wih_l^T on tensor cores (fp16 3-term)
        k_cvt<<<(int)(((size_t)T * B * NHID / 4) / 256), 256>>>(
            (const float4*)xin, xh, xl);
        k_mma<<<dim3(32, 32), 256, DEC_SMEM>>>(xh, xl, wihh + l * WIH_L,
                                               wihl + l * WIH_L, nullptr, xg,
                                               NB * 4 * BS);
        k_rec<<<NCTA, 256, SMEM_REC>>>(xg, Whh_l, bih_l, bhh_l,
                                       h0 + (size_t)l * B * NHID,
                                       c0 + (size_t)l * B * NHID,
                                       wq, bq, wk, bk, wv, bv, wfc, bfc, lng, lnb,
                                       hbuf, hlbuf, xout,
                                       out + DECN + (size_t)l * B * NHID,
                                       out + DECN + (size_t)NLAYERS * B * NHID +
                                           (size_t)l * B * NHID);
    }
    // decoder: out = x0 @ Wd^T + bd (fp16 3-term)
    k_cvt<<<(int)(((size_t)T * B * NHID / 4) / 256), 256>>>((const float4*)x0, xh, xl);
    k_mma<<<dim3(32, 250), 256, DEC_SMEM>>>(xh, xl, wh, wl, bd, out, NTOK);
}

// round 13
// speedup vs baseline: 1.0433x; 1.0055x over previous
#include <cuda_runtime.h>
#include <cuda_fp16.h>
#include <cstdint>

#define NLAYERS 2
#define NB 4
#define BS 256
#define NHID 1024
#define NINP 1024
#define NTOK 32000
#define T 64
#define B 64
#define DK 16
#define NCTA 128

// ---------------- scratch (device globals: no allocation allowed) ----------
__device__ float g_xbuf[2][(size_t)T * B * NHID];
__device__ float g_xg[(size_t)T * B * NB * 4 * BS];
__device__ float g_h[B * NHID];
__device__ float g_hl[B * NHID];
__device__ unsigned g_flags[2 * NCTA * 32];           // per-group, one flag/128B line
__device__ unsigned short g_wh[(size_t)NTOK * NHID];  // Wd fp16 hi
__device__ unsigned short g_wl[(size_t)NTOK * NHID];  // Wd fp16 lo
__device__ unsigned short g_xh[(size_t)T * B * NHID]; // activations fp16 hi
__device__ unsigned short g_xl[(size_t)T * B * NHID]; // activations fp16 lo
__device__ unsigned short g_wihh[(size_t)NLAYERS * NB * 4 * BS * NINP]; // Wih hi
__device__ unsigned short g_wihl[(size_t)NLAYERS * NB * 4 * BS * NINP]; // Wih lo

// ---------------- f32x2 helpers ---------------------------------------------
__device__ __forceinline__ unsigned long long splat2(float a) {
    unsigned long long r;
    unsigned int u = __float_as_uint(a);
    asm("mov.b64 %0, {%1, %1};" : "=l"(r) : "r"(u));
    return r;
}
__device__ __forceinline__ unsigned long long pack2(float x, float y) {
    unsigned long long r;
    asm("mov.b64 %0, {%1, %2};" : "=l"(r)
        : "r"(__float_as_uint(x)), "r"(__float_as_uint(y)));
    return r;
}
__device__ __forceinline__ void ffma2(unsigned long long &c, unsigned long long a,
                                      unsigned long long b) {
    asm("fma.rn.f32x2 %0, %1, %2, %0;" : "+l"(c) : "l"(a), "l"(b));
}
__device__ __forceinline__ float2 unpk(unsigned long long v) {
    unsigned int x, y;
    asm("mov.b64 {%0, %1}, %2;" : "=r"(x), "=r"(y) : "l"(v));
    return make_float2(__uint_as_float(x), __uint_as_float(y));
}
__device__ __forceinline__ float sigmoidf_(float x) { return 1.f / (1.f + expf(-x)); }

// ---------------- fp32 -> (hi, lo) fp16 split precompute ---------------------
__global__ void k_cvt(const float4* __restrict__ src,
                      unsigned short* __restrict__ hi,
                      unsigned short* __restrict__ lo) {
    size_t idx = (size_t)blockIdx.x * blockDim.x + threadIdx.x;
    float4 v = src[idx];
    float f[4] = {v.x, v.y, v.z, v.w};
    __half h[4], l[4];
#pragma unroll
    for (int i = 0; i < 4; ++i) {
        h[i] = __float2half_rn(f[i]);
        l[i] = __float2half_rn(f[i] - __half2float(h[i]));
    }
    uint2 hp, lp;
    hp.x = ((uint32_t)*(unsigned short*)&h[1] << 16) | *(unsigned short*)&h[0];
    hp.y = ((uint32_t)*(unsigned short*)&h[3] << 16) | *(unsigned short*)&h[2];
    lp.x = ((uint32_t)*(unsigned short*)&l[1] << 16) | *(unsigned short*)&l[0];
    lp.y = ((uint32_t)*(unsigned short*)&l[3] << 16) | *(unsigned short*)&l[2];
    *(uint2*)(hi + idx * 4) = hp;
    *(uint2*)(lo + idx * 4) = lp;
}

// ---------------- HMMA fp16 + ldmatrix + cp.async helpers --------------------
__device__ __forceinline__ void mma16816(float* d, uint32_t a0, uint32_t a1,
                                         uint32_t a2, uint32_t a3,
                                         uint32_t b0, uint32_t b1) {
    asm volatile(
        "mma.sync.aligned.m16n8k16.row.col.f32.f16.f16.f32 "
        "{%0,%1,%2,%3},{%4,%5,%6,%7},{%8,%9},{%0,%1,%2,%3};"
        : "+f"(d[0]), "+f"(d[1]), "+f"(d[2]), "+f"(d[3])
        : "r"(a0), "r"(a1), "r"(a2), "r"(a3), "r"(b0), "r"(b1));
}
__device__ __forceinline__ uint32_t smem_u32(const void* p) {
    uint32_t a;
    asm("{ .reg .u64 t; cvta.to.shared.u64 t, %1; cvt.u32.u64 %0, t; }"
        : "=r"(a) : "l"(p));
    return a;
}
__device__ __forceinline__ void ldsm4(uint32_t &r0, uint32_t &r1, uint32_t &r2,
                                      uint32_t &r3, uint32_t addr) {
    asm volatile("ldmatrix.sync.aligned.m8n8.x4.shared.b16 {%0,%1,%2,%3},[%4];"
                 : "=r"(r0), "=r"(r1), "=r"(r2), "=r"(r3) : "r"(addr));
}
__device__ __forceinline__ void ldsm2(uint32_t &r0, uint32_t &r1, uint32_t addr) {
    asm volatile("ldmatrix.sync.aligned.m8n8.x2.shared.b16 {%0,%1},[%2];"
                 : "=r"(r0), "=r"(r1) : "r"(addr));
}
__device__ __forceinline__ void cpasync16(uint32_t dst, const void* src) {
    asm volatile("cp.async.cg.shared.global [%0], [%1], 16;"
                 :: "r"(dst), "l"(src) : "memory");
}
#define CP_COMMIT() asm volatile("cp.async.commit_group;" ::: "memory")
#define CP_WAIT1() asm volatile("cp.async.wait_group 1;" ::: "memory")
#define CP_WAIT0() asm volatile("cp.async.wait_group 0;" ::: "memory")

// ---------------- tensor-core GEMM (fp16 3-term, cp.async pipeline) ----------
#define DEC_SMEM (2 * 40960)
__global__ void __launch_bounds__(256, 2) k_mma(
    const unsigned short* __restrict__ Xh, const unsigned short* __restrict__ Xl,
    const unsigned short* __restrict__ Wh, const unsigned short* __restrict__ Wl,
    const float* __restrict__ bias, float* __restrict__ out, int ldc) {
    extern __shared__ char sm[];
    const uint32_t sbase = smem_u32(sm);
    const int tid = threadIdx.x;
    const int wid = tid >> 5, lid = tid & 31;
    const int m0 = blockIdx.x * 128;
    const int n0 = blockIdx.y * 128;
    const int warpM = wid >> 2;
    const int warpN = wid & 3;
    const int laneR = lid >> 2;
    const int laneC2 = (lid & 3) * 2;
    const uint32_t aoff = (uint32_t)((lid & 15) * 80 + (lid >> 4) * 16);
    const uint32_t boff = (uint32_t)((lid & 7) * 80 + ((lid >> 3) & 1) * 16);

    const int lrow = tid >> 1;
    const int lseg = tid & 1;
    const unsigned short* arh = Xh + (size_t)(m0 + lrow) * 1024 + lseg * 16;
    const unsigned short* arl = Xl + (size_t)(m0 + lrow) * 1024 + lseg * 16;
    const unsigned short* brh = Wh + (size_t)(n0 + lrow) * 1024 + lseg * 16;
    const unsigned short* brl = Wl + (size_t)(n0 + lrow) * 1024 + lseg * 16;
    const uint32_t sdst = sbase + (uint32_t)(lrow * 80 + lseg * 32);

    float acc[4][4][4];
#pragma unroll
    for (int a = 0; a < 4; ++a)
#pragma unroll
        for (int b = 0; b < 4; ++b)
#pragma unroll
            for (int c = 0; c < 4; ++c) acc[a][b][c] = 0.f;

    auto issue = [&](int kc, int b) {
        uint32_t base = sdst + (uint32_t)b * 40960u;
        int koff = kc * 32;
        cpasync16(base, arh + koff);
        cpasync16(base + 16, arh + koff + 8);
        cpasync16(base + 10240, arl + koff);
        cpasync16(base + 10240 + 16, arl + koff + 8);
        cpasync16(base + 20480, brh + koff);
        cpasync16(base + 20480 + 16, brh + koff + 8);
        cpasync16(base + 30720, brl + koff);
        cpasync16(base + 30720 + 16, brl + koff + 8);
        CP_COMMIT();
    };
    issue(0, 0);
    issue(1, 1);

    const int NCH = 1024 / 32;
    for (int kc = 0; kc < NCH; ++kc) {
        if (kc < NCH - 1) { CP_WAIT1(); } else { CP_WAIT0(); }
        __syncthreads();
        const uint32_t bufoff = (uint32_t)(kc & 1) * 40960u;
#pragma unroll
        for (int ks = 0; ks < 2; ++ks) {
            uint32_t ah[4][4], al[4][4], bh[4][2], bl[4][2];
#pragma unroll
            for (int mt = 0; mt < 4; ++mt) {
                uint32_t ad = sbase + bufoff +
                              (uint32_t)((warpM * 64 + mt * 16) * 80 + ks * 32) + aoff;
                ldsm4(ah[mt][0], ah[mt][1], ah[mt][2], ah[mt][3], ad);
                ldsm4(al[mt][0], al[mt][1], al[mt][2], al[mt][3], ad + 10240);
            }
#pragma unroll
            for (int nt = 0; nt < 4; ++nt) {
                uint32_t bd_ = sbase + bufoff + 20480u +
                               (uint32_t)((warpN * 32 + nt * 8) * 80 + ks * 32) + boff;
                ldsm2(bh[nt][0], bh[nt][1], bd_);
                ldsm2(bl[nt][0], bl[nt][1], bd_ + 10240);
            }
#pragma unroll
            for (int mt = 0; mt < 4; ++mt)
#pragma unroll
                for (int nt = 0; nt < 4; ++nt)
                    mma16816(acc[mt][nt], ah[mt][0], ah[mt][1], ah[mt][2], ah[mt][3],
                             bh[nt][0], bh[nt][1]);
#pragma unroll
            for (int mt = 0; mt < 4; ++mt)
#pragma unroll
                for (int nt = 0; nt < 4; ++nt)
                    mma16816(acc[mt][nt], ah[mt][0], ah[mt][1], ah[mt][2], ah[mt][3],
                             bl[nt][0], bl[nt][1]);
#pragma unroll
            for (int mt = 0; mt < 4; ++mt)
#pragma unroll
                for (int nt = 0; nt < 4; ++nt)
                    mma16816(acc[mt][nt], al[mt][0], al[mt][1], al[mt][2], al[mt][3],
                             bh[nt][0], bh[nt][1]);
        }
        __syncthreads();
        if (kc + 2 < NCH) issue(kc + 2, kc & 1);
    }

#pragma unroll
    for (int mt = 0; mt < 4; ++mt) {
        int m = m0 + warpM * 64 + mt * 16 + laneR;
#pragma unroll
        for (int nt = 0; nt < 4; ++nt) {
            int n = n0 + warpN * 32 + nt * 8 + laneC2;
            float bx = 0.f, by = 0.f;
            if (bias) { bx = bias[n]; by = bias[n + 1]; }
            *(float2*)(out + (size_t)m * ldc + n) =
                make_float2(acc[mt][nt][0] + bx, acc[mt][nt][1] + by);
            *(float2*)(out + (size_t)(m + 8) * ldc + n) =
                make_float2(acc[mt][nt][2] + bx, acc[mt][nt][3] + by);
        }
    }
}

// ---------------- embedding gather ------------------------------------------
__global__ void k_embed(const int* __restrict__ tokens, const float* __restrict__ embW,
                        float* __restrict__ x) {
    int tb = blockIdx.x;
    int tok = tokens[tb];
    const float4* src = (const float4*)(embW + (size_t)tok * NINP);
    float4* dst = (float4*)(x + (size_t)tb * NINP);
    dst[threadIdx.x] = src[threadIdx.x];
}

// ---------------- persistent recurrence v4: warp-specialized batch groups ----
// 128 CTAs x 256 threads. Warps 0-3 = group A (batches 0-31), warps 4-7 =
// group B (batches 32-63). Each group runs an independent recurrence with its
// own grid barrier; barrier stalls of one group overlap compute of the other.
#define SMEM_REC (45184 * 4)
__global__ void __launch_bounds__(256, 1) k_rec(
    const float* __restrict__ xg, const float* __restrict__ Whh_l,
    const float* __restrict__ bih_l, const float* __restrict__ bhh_l,
    const float* __restrict__ h0_l, const float* __restrict__ c0_l,
    const float* __restrict__ wq, const float* __restrict__ bq,
    const float* __restrict__ wk, const float* __restrict__ bk,
    const float* __restrict__ wv, const float* __restrict__ bv,
    const float* __restrict__ wfc, const float* __restrict__ bfc,
    const float* __restrict__ lng, const float* __restrict__ lnb,
    float* __restrict__ hbuf, float* __restrict__ hlbuf,
    float* __restrict__ ys,
    float* __restrict__ outH, float* __restrict__ outC) {
    extern __shared__ float smf[];
    float* swf  = smf;             // Whh slice [256 k][36 cols]    9216
    // per-group gates h tiles [32 rows][260]:
    //   group g base = smf + 9216 + g*8320
    // per-group MHA sh buffers (1088 each) at smf + 25856 + g*1088
    float* smw  = smf + 28032;     // q/k/v weights [48][256]       12288
    float* swfc = smf + 40320;     // wfc [256][16]                 4096
    float* sbfc = smf + 44416;
    float* slng = smf + 44672;
    float* slnb = smf + 44928;

    __shared__ float sq2[2][DK], skk2[2][NB][DK], svv2[2][NB][DK];
    __shared__ float ssc2[2][NB], sp2[2][NB], so2[2][DK], sredh[2][4];

    const int tid = threadIdx.x;
    const int r = blockIdx.x;
    const int n = r & 3;
    const int j0 = (r >> 2) * 8;
    const int g = tid >> 7;          // group 0/1
    const int lt = tid & 127;        // thread within group
    const int tj = lt & 7, tb2l = lt >> 3;   // tb2l: 0..15, 2 batches each
    const int j = j0 + tj;
    const int lane = tid & 31;
    const int bA = g * 32 + tb2l * 2;        // first global batch of this thread

    float* sg = smf + 9216 + g * 8320;       // group gates tile [32][260]
    float* sh = smf + 25856 + g * 1088;      // group MHA buffer

    // ---- one-time preloads (full CTA) ----
    {
        const float* W = Whh_l + (size_t)n * 4 * BS * BS;
#pragma unroll
        for (int e = 0; e < 8; ++e) {
            int idx = e * 256 + tid;
            int col = idx >> 6, kq = idx & 63;
            int gg = col & 3, jj = col >> 2;
            float4 v = *(const float4*)(W + (size_t)(gg * BS + j0 + jj) * BS + kq * 4);
            swf[(kq * 4 + 0) * 36 + col] = v.x;
            swf[(kq * 4 + 1) * 36 + col] = v.y;
            swf[(kq * 4 + 2) * 36 + col] = v.z;
            swf[(kq * 4 + 3) * 36 + col] = v.w;
        }
#pragma unroll
        for (int i = 0; i < 4; ++i) {
            ((float4*)smw)[tid + i * 256] = ((const float4*)wq)[tid + i * 256];
            ((float4*)(smw + 4096))[tid + i * 256] = ((const float4*)wk)[tid + i * 256];
            ((float4*)(smw + 8192))[tid + i * 256] = ((const float4*)wv)[tid + i * 256];
            ((float4*)swfc)[tid + i * 256] = ((const float4*)wfc)[tid + i * 256];
        }
        sbfc[tid] = bfc[tid];
        slng[tid] = lng[tid];
        slnb[tid] = lnb[tid];
    }

    const float b_i = bih_l[n * 4 * BS + 0 * BS + j] + bhh_l[n * 4 * BS + 0 * BS + j];
    const float b_f = bih_l[n * 4 * BS + 1 * BS + j] + bhh_l[n * 4 * BS + 1 * BS + j];
    const float b_g = bih_l[n * 4 * BS + 2 * BS + j] + bhh_l[n * 4 * BS + 2 * BS + j];
    const float b_o = bih_l[n * 4 * BS + 3 * BS + j] + bhh_l[n * 4 * BS + 3 * BS + j];
    float creg[2];
    creg[0] = c0_l[(bA + 0) * NHID + n * BS + j];
    creg[1] = c0_l[(bA + 1) * NHID + n * BS + j];

    unsigned* flags = g_flags + (size_t)g * NCTA * 32;
    unsigned bgen = flags[r * 32];

    // h0 publish (full CTA), then joint sync so both halves' stores precede
    // either group's first barrier arrival.
    {
        int base = (r * 256 + tid) * 2;
        float2 v = *(const float2*)(h0_l + base);
        __stcg((float2*)(hbuf + base), v);
    }

    float xgv[2][4];
    {
#pragma unroll
        for (int bi = 0; bi < 2; ++bi) {
            const float* xr = xg + (size_t)(bA + bi) * 4096 + n * 1024 + j;
            xgv[bi][0] = __ldg(xr);       xgv[bi][1] = __ldg(xr + 256);
            xgv[bi][2] = __ldg(xr + 512); xgv[bi][3] = __ldg(xr + 768);
        }
    }
    __syncthreads();

#define HBAR() asm volatile("bar.sync %0, 128;" :: "r"(g + 1) : "memory")
    // per-group grid barrier (flat release/acquire on padded lines)
    auto gbar = [&]() {
        HBAR();
        ++bgen;
        if (lt == 0) {
            asm volatile("st.release.gpu.global.u32 [%0], %1;"
                         :: "l"(&flags[r * 32]), "r"(bgen) : "memory");
        }
        {
            unsigned v;
            do {
                asm volatile("ld.acquire.gpu.global.u32 %0, [%1];"
                             : "=r"(v) : "l"(&flags[lt * 32]) : "memory");
            } while (v < bgen);
        }
        HBAR();
    };
    gbar();

    // MHA item for this group: n2 = r&3, b2 = g*32 + (r>>2)
    const int nn2 = r & 3;
    const int bb2 = g * 32 + (r >> 2);

    for (int t = 0; t < T; ++t) {
        // ===== gates phase (group's 32 batches) =====
#pragma unroll 4
        for (int i = 0; i < 16; ++i) {
            int idx = lt + i * 128;          // 0..2047
            int bbl = idx >> 6, kq = idx & 63;
            float4 v = __ldcg((const float4*)(hbuf +
                              (size_t)(g * 32 + bbl) * NHID + n * BS) + kq);
            *(float4*)&sg[bbl * 260 + kq * 4] = v;
        }
        HBAR();

        unsigned long long a00 = pack2(xgv[0][0] + b_i, xgv[0][1] + b_f);
        unsigned long long a01 = pack2(xgv[0][2] + b_g, xgv[0][3] + b_o);
        unsigned long long a10 = pack2(xgv[1][0] + b_i, xgv[1][1] + b_f);
        unsigned long long a11 = pack2(xgv[1][2] + b_g, xgv[1][3] + b_o);
        const float* s0 = &sg[(tb2l * 2 + 0) * 260];
        const float* s1 = &sg[(tb2l * 2 + 1) * 260];
        const float* wrow = &swf[tj * 4];
#pragma unroll 8
        for (int k = 0; k < 256; ++k) {
            ulonglong2 wv = *(const ulonglong2*)(wrow + k * 36);
            unsigned long long as0 = splat2(s0[k]);
            unsigned long long as1 = splat2(s1[k]);
            ffma2(a00, as0, wv.x); ffma2(a01, as0, wv.y);
            ffma2(a10, as1, wv.x); ffma2(a11, as1, wv.y);
        }
        {
            float2 g01 = unpk(a00), g23 = unpk(a01);
            float cn = sigmoidf_(g01.y) * creg[0] + sigmoidf_(g01.x) * tanhf(g23.x);
            creg[0] = cn;
            __stcg(hlbuf + (size_t)(bA + 0) * NHID + n * BS + j,
                   sigmoidf_(g23.y) * tanhf(cn));
            g01 = unpk(a10); g23 = unpk(a11);
            cn = sigmoidf_(g01.y) * creg[1] + sigmoidf_(g01.x) * tanhf(g23.x);
            creg[1] = cn;
            __stcg(hlbuf + (size_t)(bA + 1) * NHID + n * BS + j,
                   sigmoidf_(g23.y) * tanhf(cn));
        }
        gbar();

        // ===== MHA phase (group's single item) =====
        float* ys_t = ys + (size_t)t * B * NHID;
        {
            const float4* src = (const float4*)(hlbuf + (size_t)bb2 * NHID);
            ((float4*)sh)[lt] = __ldcg(src + lt);
            ((float4*)sh)[lt + 128] = __ldcg(src + lt + 128);
        }
        HBAR();
        for (int w = lt; w < 144; w += 128) {
            const float *hv, *wr; float* dst; float bpv;
            if (w < 16) { wr = smw + w * 256; hv = sh + nn2 * 256;
                          dst = &sq2[g][w]; bpv = __ldg(bq + w); }
            else if (w < 80) { int m = (w - 16) >> 4, d = (w - 16) & 15;
                               wr = smw + 4096 + d * 256; hv = sh + m * 256;
                               dst = &skk2[g][m][d]; bpv = __ldg(bk + d); }
            else { int m = (w - 80) >> 4, d = (w - 80) & 15;
                   wr = smw + 8192 + d * 256; hv = sh + m * 256;
                   dst = &svv2[g][m][d]; bpv = __ldg(bv + d); }
            float a0 = 0, a1 = 0, a2 = 0, a3 = 0;
#pragma unroll 8
            for (int jj = 0; jj < 256; jj += 4) {
                a0 += hv[jj] * wr[jj];         a1 += hv[jj + 1] * wr[jj + 1];
                a2 += hv[jj + 2] * wr[jj + 2]; a3 += hv[jj + 3] * wr[jj + 3];
            }
            *dst = a0 + a1 + a2 + a3 + bpv;
        }
        HBAR();
        if (lt < 4) {
            float s = 0;
#pragma unroll
            for (int d = 0; d < DK; ++d) s += sq2[g][d] * skk2[g][lt][d];
            ssc2[g][lt] = s * 0.25f;
        }
        HBAR();
        if (lt < 4) {
            float mx = fmaxf(fmaxf(ssc2[g][0], ssc2[g][1]),
                             fmaxf(ssc2[g][2], ssc2[g][3]));
            float sum = expf(ssc2[g][0] - mx) + expf(ssc2[g][1] - mx) +
                        expf(ssc2[g][2] - mx) + expf(ssc2[g][3] - mx);
            sp2[g][lt] = expf(ssc2[g][lt] - mx) / sum;
        }
        HBAR();
        if (lt < DK) {
            float o = 0;
#pragma unroll
            for (int m = 0; m < NB; ++m) o += sp2[g][m] * svv2[g][m][lt];
            so2[g][lt] = o;
        }
        HBAR();
        float v0 = sbfc[lt] + sh[nn2 * 256 + lt];
        float v1 = sbfc[lt + 128] + sh[nn2 * 256 + lt + 128];
#pragma unroll
        for (int d = 0; d < DK; ++d) {
            v0 += so2[g][d] * swfc[lt * DK + d];
            v1 += so2[g][d] * swfc[(lt + 128) * DK + d];
        }
        float s = v0 + v1;
#pragma unroll
        for (int off = 16; off; off >>= 1) s += __shfl_down_sync(0xffffffffu, s, off);
        if (lane == 0) sredh[g][lt >> 5] = s;
        HBAR();
        float mu = (sredh[g][0] + sredh[g][1] + sredh[g][2] + sredh[g][3])
                   * (1.f / BS);
        HBAR();
        float dv0 = v0 - mu, dv1 = v1 - mu;
        float s2 = dv0 * dv0 + dv1 * dv1;
#pragma unroll
        for (int off = 16; off; off >>= 1) s2 += __shfl_down_sync(0xffffffffu, s2, off);
        if (lane == 0) sredh[g][lt >> 5] = s2;
        HBAR();
        float var = (sredh[g][0] + sredh[g][1] + sredh[g][2] + sredh[g][3])
                    * (1.f / BS);
        float rstd = rsqrtf(var + 1e-5f);
        float y0 = dv0 * rstd * slng[lt] + slnb[lt];
        float y1 = dv1 * rstd * slng[lt + 128] + slnb[lt + 128];
        int i0 = bb2 * NHID + nn2 * 256 + lt;
        __stcg(hbuf + i0, y0);       ys_t[i0] = y0;
        __stcg(hbuf + i0 + 128, y1); ys_t[i0 + 128] = y1;

        // prefetch xg for t+1 (independent of the barrier)
        if (t + 1 < T) {
            const float* xg_t = xg + (size_t)(t + 1) * B * 4096;
#pragma unroll
            for (int bi = 0; bi < 2; ++bi) {
                const float* xr = xg_t + (size_t)(bA + bi) * 4096 + n * 1024 + j;
                xgv[bi][0] = __ldg(xr);       xgv[bi][1] = __ldg(xr + 256);
                xgv[bi][2] = __ldg(xr + 512); xgv[bi][3] = __ldg(xr + 768);
            }
        }
        gbar();
    }

    // final writeout: both groups have passed their final barriers; join CTA.
    __syncthreads();
    {
        int base = (r * 256 + tid) * 2;
        float2 v = __ldcg((const float2*)(hbuf + base));
        *(float2*)(outH + base) = v;
    }
    outC[(bA + 0) * NHID + n * BS + j] = creg[0];
    outC[(bA + 1) * NHID + n * BS + j] = creg[1];
#undef HBAR
}

// ---------------- host driver ------------------------------------------------
extern "C" void kernel_launch(void* const* d_in, const int* in_sizes, int n_in,
                              void* d_out, int out_size) {
    const int* tokens = (const int*)d_in[0];
    const float* h0 = (const float*)d_in[1];
    const float* c0 = (const float*)d_in[2];
    const float* embW = (const float*)d_in[3];
    const float* Wih = (const float*)d_in[4];
    const float* Whh = (const float*)d_in[5];
    const float* bih = (const float*)d_in[6];
    const float* bhh = (const float*)d_in[7];
    const float* wq = (const float*)d_in[8];
    const float* bq = (const float*)d_in[9];
    const float* wk = (const float*)d_in[10];
    const float* bk = (const float*)d_in[11];
    const float* wv = (const float*)d_in[12];
    const float* bv = (const float*)d_in[13];
    const float* wfc = (const float*)d_in[14];
    const float* bfc = (const float*)d_in[15];
    const float* lng = (const float*)d_in[16];
    const float* lnb = (const float*)d_in[17];
    const float* Wd = (const float*)d_in[18];
    const float* bd = (const float*)d_in[19];
    float* out = (float*)d_out;

    static int attr_set = 0;
    if (!attr_set) {
        cudaFuncSetAttribute(k_rec, cudaFuncAttributeMaxDynamicSharedMemorySize,
                             SMEM_REC);
        cudaFuncSetAttribute(k_mma, cudaFuncAttributeMaxDynamicSharedMemorySize,
                             DEC_SMEM);
        attr_set = 1;
    }

    float *xb, *xg, *hbuf, *hlbuf;
    unsigned short *wh, *wl, *xh, *xl, *wihh, *wihl;
    cudaGetSymbolAddress((void**)&xb, g_xbuf);
    cudaGetSymbolAddress((void**)&xg, g_xg);
    cudaGetSymbolAddress((void**)&hbuf, g_h);
    cudaGetSymbolAddress((void**)&hlbuf, g_hl);
    cudaGetSymbolAddress((void**)&wh, g_wh);
    cudaGetSymbolAddress((void**)&wl, g_wl);
    cudaGetSymbolAddress((void**)&xh, g_xh);
    cudaGetSymbolAddress((void**)&xl, g_xl);
    cudaGetSymbolAddress((void**)&wihh, g_wihh);
    cudaGetSymbolAddress((void**)&wihl, g_wihl);
    float* x0 = xb;
    float* x1 = xb + (size_t)T * B * NHID;

    // weight conversions (fp16 hi/lo planes)
    k_cvt<<<(int)(((size_t)NTOK * NHID / 4) / 256), 256>>>((const float4*)Wd, wh, wl);
    k_cvt<<<(int)(((size_t)NLAYERS * NB * 4 * BS * NINP / 4) / 256), 256>>>(
        (const float4*)Wih, wihh, wihl);

    k_embed<<<T * B, 256>>>(tokens, embW, x0);

    const size_t DECN = (size_t)T * B * NTOK;
    const size_t WIH_L = (size_t)NB * 4 * BS * NINP;
    for (int l = 0; l < NLAYERS; ++l) {
        const float* xin = (l == 0) ? x0 : x1;
        float* xout = (l == 0) ? x1 : x0;
        const float* Whh_l = Whh + (size_t)l * NB * 4 * BS * BS;
        const float* bih_l = bih + (size_t)l * NB * 4 * BS;
        const float* bhh_l = bhh + (size_t)l * NB * 4 * BS;
        // xg = xin @ Wih_l^T on tensor cores (fp16 3-term)
        k_cvt<<<(int)(((size_t)T * B * NHID / 4) / 256), 256>>>(
            (const float4*)xin, xh, xl);
        k_mma<<<dim3(32, 32), 256, DEC_SMEM>>>(xh, xl, wihh + l * WIH_L,
                                               wihl + l * WIH_L, nullptr, xg,
                                               NB * 4 * BS);
        k_rec<<<NCTA, 256, SMEM_REC>>>(xg, Whh_l, bih_l, bhh_l,
                                       h0 + (size_t)l * B * NHID,
                                       c0 + (size_t)l * B * NHID,
                                       wq, bq, wk, bk, wv, bv, wfc, bfc, lng, lnb,
                                       hbuf, hlbuf, xout,
                                       out + DECN + (size_t)l * B * NHID,
                                       out + DECN + (size_t)NLAYERS * B * NHID +
                                           (size_t)l * B * NHID);
    }
    // decoder: out = x0 @ Wd^T + bd (fp16 3-term)
    k_cvt<<<(int)(((size_t)T * B * NHID / 4) / 256), 256>>>((const float4*)x0, xh, xl);
    k_mma<<<dim3(32, 250), 256, DEC_SMEM>>>(xh, xl, wh, wl, bd, out, NTOK);
}

// round 14
// speedup vs baseline: 1.1618x; 1.1136x over previous
#include <cuda_runtime.h>
#include <cuda_fp16.h>
#include <cstdint>

#define NLAYERS 2
#define NB 4
#define BS 256
#define NHID 1024
#define NINP 1024
#define NTOK 32000
#define T 64
#define B 64
#define DK 16
#define NCTA 128

// ---------------- scratch (device globals: no allocation allowed) ----------
__device__ float g_xg[(size_t)T * B * NB * 4 * BS];
__device__ float g_h[B * NHID];
__device__ float g_hl[B * NHID];
__device__ unsigned g_flags[2 * NCTA * 32];           // per-group, one flag/128B line
__device__ unsigned short g_wh[(size_t)NTOK * NHID];  // Wd fp16 hi
__device__ unsigned short g_wl[(size_t)NTOK * NHID];  // Wd fp16 lo
__device__ unsigned short g_xh[(size_t)T * B * NHID]; // plane buffer A hi
__device__ unsigned short g_xl[(size_t)T * B * NHID]; // plane buffer A lo
__device__ unsigned short g_yh[(size_t)T * B * NHID]; // plane buffer B hi
__device__ unsigned short g_yl[(size_t)T * B * NHID]; // plane buffer B lo
__device__ unsigned short g_wihh[(size_t)NLAYERS * NB * 4 * BS * NINP]; // Wih hi
__device__ unsigned short g_wihl[(size_t)NLAYERS * NB * 4 * BS * NINP]; // Wih lo

// ---------------- f32x2 helpers ---------------------------------------------
__device__ __forceinline__ unsigned long long splat2(float a) {
    unsigned long long r;
    unsigned int u = __float_as_uint(a);
    asm("mov.b64 %0, {%1, %1};" : "=l"(r) : "r"(u));
    return r;
}
__device__ __forceinline__ unsigned long long pack2(float x, float y) {
    unsigned long long r;
    asm("mov.b64 %0, {%1, %2};" : "=l"(r)
        : "r"(__float_as_uint(x)), "r"(__float_as_uint(y)));
    return r;
}
__device__ __forceinline__ void ffma2(unsigned long long &c, unsigned long long a,
                                      unsigned long long b) {
    asm("fma.rn.f32x2 %0, %1, %2, %0;" : "+l"(c) : "l"(a), "l"(b));
}
__device__ __forceinline__ float2 unpk(unsigned long long v) {
    unsigned int x, y;
    asm("mov.b64 {%0, %1}, %2;" : "=r"(x), "=r"(y) : "l"(v));
    return make_float2(__uint_as_float(x), __uint_as_float(y));
}
__device__ __forceinline__ float sigmoidf_(float x) { return 1.f / (1.f + expf(-x)); }

// ---------------- fp32 -> (hi, lo) fp16 split precompute (weights) -----------
__global__ void k_cvt(const float4* __restrict__ src,
                      unsigned short* __restrict__ hi,
                      unsigned short* __restrict__ lo) {
    size_t idx = (size_t)blockIdx.x * blockDim.x + threadIdx.x;
    float4 v = src[idx];
    float f[4] = {v.x, v.y, v.z, v.w};
    __half h[4], l[4];
#pragma unroll
    for (int i = 0; i < 4; ++i) {
        h[i] = __float2half_rn(f[i]);
        l[i] = __float2half_rn(f[i] - __half2float(h[i]));
    }
    uint2 hp, lp;
    hp.x = ((uint32_t)*(unsigned short*)&h[1] << 16) | *(unsigned short*)&h[0];
    hp.y = ((uint32_t)*(unsigned short*)&h[3] << 16) | *(unsigned short*)&h[2];
    lp.x = ((uint32_t)*(unsigned short*)&l[1] << 16) | *(unsigned short*)&l[0];
    lp.y = ((uint32_t)*(unsigned short*)&l[3] << 16) | *(unsigned short*)&l[2];
    *(uint2*)(hi + idx * 4) = hp;
    *(uint2*)(lo + idx * 4) = lp;
}

// ---------------- HMMA fp16 + ldmatrix + cp.async helpers --------------------
__device__ __forceinline__ void mma16816(float* d, uint32_t a0, uint32_t a1,
                                         uint32_t a2, uint32_t a3,
                                         uint32_t b0, uint32_t b1) {
    asm volatile(
        "mma.sync.aligned.m16n8k16.row.col.f32.f16.f16.f32 "
        "{%0,%1,%2,%3},{%4,%5,%6,%7},{%8,%9},{%0,%1,%2,%3};"
        : "+f"(d[0]), "+f"(d[1]), "+f"(d[2]), "+f"(d[3])
        : "r"(a0), "r"(a1), "r"(a2), "r"(a3), "r"(b0), "r"(b1));
}
__device__ __forceinline__ uint32_t smem_u32(const void* p) {
    uint32_t a;
    asm("{ .reg .u64 t; cvta.to.shared.u64 t, %1; cvt.u32.u64 %0, t; }"
        : "=r"(a) : "l"(p));
    return a;
}
__device__ __forceinline__ void ldsm4(uint32_t &r0, uint32_t &r1, uint32_t &r2,
                                      uint32_t &r3, uint32_t addr) {
    asm volatile("ldmatrix.sync.aligned.m8n8.x4.shared.b16 {%0,%1,%2,%3},[%4];"
                 : "=r"(r0), "=r"(r1), "=r"(r2), "=r"(r3) : "r"(addr));
}
__device__ __forceinline__ void ldsm2(uint32_t &r0, uint32_t &r1, uint32_t addr) {
    asm volatile("ldmatrix.sync.aligned.m8n8.x2.shared.b16 {%0,%1},[%2];"
                 : "=r"(r0), "=r"(r1) : "r"(addr));
}
__device__ __forceinline__ void cpasync16(uint32_t dst, const void* src) {
    asm volatile("cp.async.cg.shared.global [%0], [%1], 16;"
                 :: "r"(dst), "l"(src) : "memory");
}
#define CP_COMMIT() asm volatile("cp.async.commit_group;" ::: "memory")
#define CP_WAIT1() asm volatile("cp.async.wait_group 1;" ::: "memory")
#define CP_WAIT0() asm volatile("cp.async.wait_group 0;" ::: "memory")

// ---------------- tensor-core GEMM (fp16 split, cp.async pipeline) -----------
// THREE=true : D = Ah*Bh + Ah*Bl + Al*Bh (3-term, near-fp32; for xg)
// THREE=false: D = Ah*Bh + Ah*Bl       (2-term, ~2^-12 rel; for decoder)
#define DEC_SMEM (2 * 40960)
template <bool THREE>
__global__ void __launch_bounds__(256, 2) k_mma(
    const unsigned short* __restrict__ Xh, const unsigned short* __restrict__ Xl,
    const unsigned short* __restrict__ Wh, const unsigned short* __restrict__ Wl,
    const float* __restrict__ bias, float* __restrict__ out, int ldc) {
    extern __shared__ char sm[];
    const uint32_t sbase = smem_u32(sm);
    const int tid = threadIdx.x;
    const int wid = tid >> 5, lid = tid & 31;
    const int m0 = blockIdx.x * 128;
    const int n0 = blockIdx.y * 128;
    const int warpM = wid >> 2;
    const int warpN = wid & 3;
    const int laneR = lid >> 2;
    const int laneC2 = (lid & 3) * 2;
    const uint32_t aoff = (uint32_t)((lid & 15) * 80 + (lid >> 4) * 16);
    const uint32_t boff = (uint32_t)((lid & 7) * 80 + ((lid >> 3) & 1) * 16);

    const int lrow = tid >> 1;
    const int lseg = tid & 1;
    const unsigned short* arh = Xh + (size_t)(m0 + lrow) * 1024 + lseg * 16;
    const unsigned short* arl = Xl + (size_t)(m0 + lrow) * 1024 + lseg * 16;
    const unsigned short* brh = Wh + (size_t)(n0 + lrow) * 1024 + lseg * 16;
    const unsigned short* brl = Wl + (size_t)(n0 + lrow) * 1024 + lseg * 16;
    const uint32_t sdst = sbase + (uint32_t)(lrow * 80 + lseg * 32);

    float acc[4][4][4];
#pragma unroll
    for (int a = 0; a < 4; ++a)
#pragma unroll
        for (int b = 0; b < 4; ++b)
#pragma unroll
            for (int c = 0; c < 4; ++c) acc[a][b][c] = 0.f;

    auto issue = [&](int kc, int b) {
        uint32_t base = sdst + (uint32_t)b * 40960u;
        int koff = kc * 32;
        cpasync16(base, arh + koff);
        cpasync16(base + 16, arh + koff + 8);
        if (THREE) {
            cpasync16(base + 10240, arl + koff);
            cpasync16(base + 10240 + 16, arl + koff + 8);
        }
        cpasync16(base + 20480, brh + koff);
        cpasync16(base + 20480 + 16, brh + koff + 8);
        cpasync16(base + 30720, brl + koff);
        cpasync16(base + 30720 + 16, brl + koff + 8);
        CP_COMMIT();
    };
    issue(0, 0);
    issue(1, 1);

    const int NCH = 1024 / 32;
    for (int kc = 0; kc < NCH; ++kc) {
        if (kc < NCH - 1) { CP_WAIT1(); } else { CP_WAIT0(); }
        __syncthreads();
        const uint32_t bufoff = (uint32_t)(kc & 1) * 40960u;
#pragma unroll
        for (int ks = 0; ks < 2; ++ks) {
            uint32_t ah[4][4], al[4][4], bh[4][2], bl[4][2];
#pragma unroll
            for (int mt = 0; mt < 4; ++mt) {
                uint32_t ad = sbase + bufoff +
                              (uint32_t)((warpM * 64 + mt * 16) * 80 + ks * 32) + aoff;
                ldsm4(ah[mt][0], ah[mt][1], ah[mt][2], ah[mt][3], ad);
                if (THREE)
                    ldsm4(al[mt][0], al[mt][1], al[mt][2], al[mt][3], ad + 10240);
            }
#pragma unroll
            for (int nt = 0; nt < 4; ++nt) {
                uint32_t bd_ = sbase + bufoff + 20480u +
                               (uint32_t)((warpN * 32 + nt * 8) * 80 + ks * 32) + boff;
                ldsm2(bh[nt][0], bh[nt][1], bd_);
                ldsm2(bl[nt][0], bl[nt][1], bd_ + 10240);
            }
#pragma unroll
            for (int mt = 0; mt < 4; ++mt)
#pragma unroll
                for (int nt = 0; nt < 4; ++nt)
                    mma16816(acc[mt][nt], ah[mt][0], ah[mt][1], ah[mt][2], ah[mt][3],
                             bh[nt][0], bh[nt][1]);
#pragma unroll
            for (int mt = 0; mt < 4; ++mt)
#pragma unroll
                for (int nt = 0; nt < 4; ++nt)
                    mma16816(acc[mt][nt], ah[mt][0], ah[mt][1], ah[mt][2], ah[mt][3],
                             bl[nt][0], bl[nt][1]);
            if (THREE) {
#pragma unroll
                for (int mt = 0; mt < 4; ++mt)
#pragma unroll
                    for (int nt = 0; nt < 4; ++nt)
                        mma16816(acc[mt][nt], al[mt][0], al[mt][1], al[mt][2],
                                 al[mt][3], bh[nt][0], bh[nt][1]);
            }
        }
        __syncthreads();
        if (kc + 2 < NCH) issue(kc + 2, kc & 1);
    }

#pragma unroll
    for (int mt = 0; mt < 4; ++mt) {
        int m = m0 + warpM * 64 + mt * 16 + laneR;
#pragma unroll
        for (int nt = 0; nt < 4; ++nt) {
            int n = n0 + warpN * 32 + nt * 8 + laneC2;
            float bx = 0.f, by = 0.f;
            if (bias) { bx = bias[n]; by = bias[n + 1]; }
            *(float2*)(out + (size_t)m * ldc + n) =
                make_float2(acc[mt][nt][0] + bx, acc[mt][nt][1] + by);
            *(float2*)(out + (size_t)(m + 8) * ldc + n) =
                make_float2(acc[mt][nt][2] + bx, acc[mt][nt][3] + by);
        }
    }
}

// ---------------- embedding gather -> fp16 hi/lo planes ----------------------
__global__ void k_embed(const int* __restrict__ tokens, const float* __restrict__ embW,
                        unsigned short* __restrict__ xh,
                        unsigned short* __restrict__ xl) {
    int tb = blockIdx.x;
    int tok = tokens[tb];
    int tid = threadIdx.x;
    float4 v = *(const float4*)(embW + (size_t)tok * NINP + tid * 4);
    float f[4] = {v.x, v.y, v.z, v.w};
    __half h[4], l[4];
#pragma unroll
    for (int i = 0; i < 4; ++i) {
        h[i] = __float2half_rn(f[i]);
        l[i] = __float2half_rn(f[i] - __half2float(h[i]));
    }
    uint2 hp, lp;
    hp.x = ((uint32_t)*(unsigned short*)&h[1] << 16) | *(unsigned short*)&h[0];
    hp.y = ((uint32_t)*(unsigned short*)&h[3] << 16) | *(unsigned short*)&h[2];
    lp.x = ((uint32_t)*(unsigned short*)&l[1] << 16) | *(unsigned short*)&l[0];
    lp.y = ((uint32_t)*(unsigned short*)&l[3] << 16) | *(unsigned short*)&l[2];
    size_t base = (size_t)tb * NINP + tid * 4;
    *(uint2*)(xh + base) = hp;
    *(uint2*)(xl + base) = lp;
}

// ---------------- persistent recurrence v4 (warp-specialized groups) ---------
#define SMEM_REC (45184 * 4)
__global__ void __launch_bounds__(256, 1) k_rec(
    const float* __restrict__ xg, const float* __restrict__ Whh_l,
    const float* __restrict__ bih_l, const float* __restrict__ bhh_l,
    const float* __restrict__ h0_l, const float* __restrict__ c0_l,
    const float* __restrict__ wq, const float* __restrict__ bq,
    const float* __restrict__ wk, const float* __restrict__ bk,
    const float* __restrict__ wv, const float* __restrict__ bv,
    const float* __restrict__ wfc, const float* __restrict__ bfc,
    const float* __restrict__ lng, const float* __restrict__ lnb,
    float* __restrict__ hbuf, float* __restrict__ hlbuf,
    unsigned short* __restrict__ ysh, unsigned short* __restrict__ ysl,
    float* __restrict__ outH, float* __restrict__ outC) {
    extern __shared__ float smf[];
    float* swf  = smf;             // Whh slice [256 k][36 cols]    9216
    float* smw  = smf + 28032;     // q/k/v weights [48][256]       12288
    float* swfc = smf + 40320;     // wfc [256][16]                 4096
    float* sbfc = smf + 44416;
    float* slng = smf + 44672;
    float* slnb = smf + 44928;

    __shared__ float sq2[2][DK], skk2[2][NB][DK], svv2[2][NB][DK];
    __shared__ float ssc2[2][NB], sp2[2][NB], so2[2][DK], sredh[2][4];

    const int tid = threadIdx.x;
    const int r = blockIdx.x;
    const int n = r & 3;
    const int j0 = (r >> 2) * 8;
    const int g = tid >> 7;
    const int lt = tid & 127;
    const int tj = lt & 7, tb2l = lt >> 3;
    const int j = j0 + tj;
    const int lane = tid & 31;
    const int bA = g * 32 + tb2l * 2;

    float* sg = smf + 9216 + g * 8320;
    float* sh = smf + 25856 + g * 1088;

    {
        const float* W = Whh_l + (size_t)n * 4 * BS * BS;
#pragma unroll
        for (int e = 0; e < 8; ++e) {
            int idx = e * 256 + tid;
            int col = idx >> 6, kq = idx & 63;
            int gg = col & 3, jj = col >> 2;
            float4 v = *(const float4*)(W + (size_t)(gg * BS + j0 + jj) * BS + kq * 4);
            swf[(kq * 4 + 0) * 36 + col] = v.x;
            swf[(kq * 4 + 1) * 36 + col] = v.y;
            swf[(kq * 4 + 2) * 36 + col] = v.z;
            swf[(kq * 4 + 3) * 36 + col] = v.w;
        }
#pragma unroll
        for (int i = 0; i < 4; ++i) {
            ((float4*)smw)[tid + i * 256] = ((const float4*)wq)[tid + i * 256];
            ((float4*)(smw + 4096))[tid + i * 256] = ((const float4*)wk)[tid + i * 256];
            ((float4*)(smw + 8192))[tid + i * 256] = ((const float4*)wv)[tid + i * 256];
            ((float4*)swfc)[tid + i * 256] = ((const float4*)wfc)[tid + i * 256];
        }
        sbfc[tid] = bfc[tid];
        slng[tid] = lng[tid];
        slnb[tid] = lnb[tid];
    }

    const float b_i = bih_l[n * 4 * BS + 0 * BS + j] + bhh_l[n * 4 * BS + 0 * BS + j];
    const float b_f = bih_l[n * 4 * BS + 1 * BS + j] + bhh_l[n * 4 * BS + 1 * BS + j];
    const float b_g = bih_l[n * 4 * BS + 2 * BS + j] + bhh_l[n * 4 * BS + 2 * BS + j];
    const float b_o = bih_l[n * 4 * BS + 3 * BS + j] + bhh_l[n * 4 * BS + 3 * BS + j];
    float creg[2];
    creg[0] = c0_l[(bA + 0) * NHID + n * BS + j];
    creg[1] = c0_l[(bA + 1) * NHID + n * BS + j];

    unsigned* flags = g_flags + (size_t)g * NCTA * 32;
    unsigned bgen = flags[r * 32];

    {
        int base = (r * 256 + tid) * 2;
        float2 v = *(const float2*)(h0_l + base);
        __stcg((float2*)(hbuf + base), v);
    }

    float xgv[2][4];
    {
#pragma unroll
        for (int bi = 0; bi < 2; ++bi) {
            const float* xr = xg + (size_t)(bA + bi) * 4096 + n * 1024 + j;
            xgv[bi][0] = __ldg(xr);       xgv[bi][1] = __ldg(xr + 256);
            xgv[bi][2] = __ldg(xr + 512); xgv[bi][3] = __ldg(xr + 768);
        }
    }
    __syncthreads();

#define HBAR() asm volatile("bar.sync %0, 128;" :: "r"(g + 1) : "memory")
    auto gbar = [&]() {
        HBAR();
        ++bgen;
        if (lt == 0) {
            asm volatile("st.release.gpu.global.u32 [%0], %1;"
                         :: "l"(&flags[r * 32]), "r"(bgen) : "memory");
        }
        {
            unsigned v;
            do {
                asm volatile("ld.acquire.gpu.global.u32 %0, [%1];"
                             : "=r"(v) : "l"(&flags[lt * 32]) : "memory");
            } while (v < bgen);
        }
        HBAR();
    };
    gbar();

    const int nn2 = r & 3;
    const int bb2 = g * 32 + (r >> 2);

    for (int t = 0; t < T; ++t) {
#pragma unroll 4
        for (int i = 0; i < 16; ++i) {
            int idx = lt + i * 128;
            int bbl = idx >> 6, kq = idx & 63;
            float4 v = __ldcg((const float4*)(hbuf +
                              (size_t)(g * 32 + bbl) * NHID + n * BS) + kq);
            *(float4*)&sg[bbl * 260 + kq * 4] = v;
        }
        HBAR();

        unsigned long long a00 = pack2(xgv[0][0] + b_i, xgv[0][1] + b_f);
        unsigned long long a01 = pack2(xgv[0][2] + b_g, xgv[0][3] + b_o);
        unsigned long long a10 = pack2(xgv[1][0] + b_i, xgv[1][1] + b_f);
        unsigned long long a11 = pack2(xgv[1][2] + b_g, xgv[1][3] + b_o);
        const float* s0 = &sg[(tb2l * 2 + 0) * 260];
        const float* s1 = &sg[(tb2l * 2 + 1) * 260];
        const float* wrow = &swf[tj * 4];
#pragma unroll 8
        for (int k = 0; k < 256; ++k) {
            ulonglong2 wv = *(const ulonglong2*)(wrow + k * 36);
            unsigned long long as0 = splat2(s0[k]);
            unsigned long long as1 = splat2(s1[k]);
            ffma2(a00, as0, wv.x); ffma2(a01, as0, wv.y);
            ffma2(a10, as1, wv.x); ffma2(a11, as1, wv.y);
        }
        {
            float2 g01 = unpk(a00), g23 = unpk(a01);
            float cn = sigmoidf_(g01.y) * creg[0] + sigmoidf_(g01.x) * tanhf(g23.x);
            creg[0] = cn;
            __stcg(hlbuf + (size_t)(bA + 0) * NHID + n * BS + j,
                   sigmoidf_(g23.y) * tanhf(cn));
            g01 = unpk(a10); g23 = unpk(a11);
            cn = sigmoidf_(g01.y) * creg[1] + sigmoidf_(g01.x) * tanhf(g23.x);
            creg[1] = cn;
            __stcg(hlbuf + (size_t)(bA + 1) * NHID + n * BS + j,
                   sigmoidf_(g23.y) * tanhf(cn));
        }
        gbar();

        {
            const float4* src = (const float4*)(hlbuf + (size_t)bb2 * NHID);
            ((float4*)sh)[lt] = __ldcg(src + lt);
            ((float4*)sh)[lt + 128] = __ldcg(src + lt + 128);
        }
        HBAR();
        for (int w = lt; w < 144; w += 128) {
            const float *hv, *wr; float* dst; float bpv;
            if (w < 16) { wr = smw + w * 256; hv = sh + nn2 * 256;
                          dst = &sq2[g][w]; bpv = __ldg(bq + w); }
            else if (w < 80) { int m = (w - 16) >> 4, d = (w - 16) & 15;
                               wr = smw + 4096 + d * 256; hv = sh + m * 256;
                               dst = &skk2[g][m][d]; bpv = __ldg(bk + d); }
            else { int m = (w - 80) >> 4, d = (w - 80) & 15;
                   wr = smw + 8192 + d * 256; hv = sh + m * 256;
                   dst = &svv2[g][m][d]; bpv = __ldg(bv + d); }
            float a0 = 0, a1 = 0, a2 = 0, a3 = 0;
#pragma unroll 8
            for (int jj = 0; jj < 256; jj += 4) {
                a0 += hv[jj] * wr[jj];         a1 += hv[jj + 1] * wr[jj + 1];
                a2 += hv[jj + 2] * wr[jj + 2]; a3 += hv[jj + 3] * wr[jj + 3];
            }
            *dst = a0 + a1 + a2 + a3 + bpv;
        }
        HBAR();
        if (lt < 4) {
            float s = 0;
#pragma unroll
            for (int d = 0; d < DK; ++d) s += sq2[g][d] * skk2[g][lt][d];
            ssc2[g][lt] = s * 0.25f;
        }
        HBAR();
        if (lt < 4) {
            float mx = fmaxf(fmaxf(ssc2[g][0], ssc2[g][1]),
                             fmaxf(ssc2[g][2], ssc2[g][3]));
            float sum = expf(ssc2[g][0] - mx) + expf(ssc2[g][1] - mx) +
                        expf(ssc2[g][2] - mx) + expf(ssc2[g][3] - mx);
            sp2[g][lt] = expf(ssc2[g][lt] - mx) / sum;
        }
        HBAR();
        if (lt < DK) {
            float o = 0;
#pragma unroll
            for (int m = 0; m < NB; ++m) o += sp2[g][m] * svv2[g][m][lt];
            so2[g][lt] = o;
        }
        HBAR();
        float v0 = sbfc[lt] + sh[nn2 * 256 + lt];
        float v1 = sbfc[lt + 128] + sh[nn2 * 256 + lt + 128];
#pragma unroll
        for (int d = 0; d < DK; ++d) {
            v0 += so2[g][d] * swfc[lt * DK + d];
            v1 += so2[g][d] * swfc[(lt + 128) * DK + d];
        }
        float s = v0 + v1;
#pragma unroll
        for (int off = 16; off; off >>= 1) s += __shfl_down_sync(0xffffffffu, s, off);
        if (lane == 0) sredh[g][lt >> 5] = s;
        HBAR();
        float mu = (sredh[g][0] + sredh[g][1] + sredh[g][2] + sredh[g][3])
                   * (1.f / BS);
        HBAR();
        float dv0 = v0 - mu, dv1 = v1 - mu;
        float s2 = dv0 * dv0 + dv1 * dv1;
#pragma unroll
        for (int off = 16; off; off >>= 1) s2 += __shfl_down_sync(0xffffffffu, s2, off);
        if (lane == 0) sredh[g][lt >> 5] = s2;
        HBAR();
        float var = (sredh[g][0] + sredh[g][1] + sredh[g][2] + sredh[g][3])
                    * (1.f / BS);
        float rstd = rsqrtf(var + 1e-5f);
        float y0 = dv0 * rstd * slng[lt] + slnb[lt];
        float y1 = dv1 * rstd * slng[lt + 128] + slnb[lt + 128];
        int i0 = bb2 * NHID + nn2 * 256 + lt;
        __stcg(hbuf + i0, y0);
        __stcg(hbuf + i0 + 128, y1);
        // emit fp16 hi/lo planes (fused conversion)
        {
            unsigned short* ysh_t = ysh + (size_t)t * B * NHID;
            unsigned short* ysl_t = ysl + (size_t)t * B * NHID;
            __half h0_ = __float2half_rn(y0);
            __half l0_ = __float2half_rn(y0 - __half2float(h0_));
            __half h1_ = __float2half_rn(y1);
            __half l1_ = __float2half_rn(y1 - __half2float(h1_));
            ysh_t[i0] = *(unsigned short*)&h0_;
            ysl_t[i0] = *(unsigned short*)&l0_;
            ysh_t[i0 + 128] = *(unsigned short*)&h1_;
            ysl_t[i0 + 128] = *(unsigned short*)&l1_;
        }

        if (t + 1 < T) {
            const float* xg_t = xg + (size_t)(t + 1) * B * 4096;
#pragma unroll
            for (int bi = 0; bi < 2; ++bi) {
                const float* xr = xg_t + (size_t)(bA + bi) * 4096 + n * 1024 + j;
                xgv[bi][0] = __ldg(xr);       xgv[bi][1] = __ldg(xr + 256);
                xgv[bi][2] = __ldg(xr + 512); xgv[bi][3] = __ldg(xr + 768);
            }
        }
        gbar();
    }

    __syncthreads();
    {
        int base = (r * 256 + tid) * 2;
        float2 v = __ldcg((const float2*)(hbuf + base));
        *(float2*)(outH + base) = v;
    }
    outC[(bA + 0) * NHID + n * BS + j] = creg[0];
    outC[(bA + 1) * NHID + n * BS + j] = creg[1];
#undef HBAR
}

// ---------------- host driver ------------------------------------------------
extern "C" void kernel_launch(void* const* d_in, const int* in_sizes, int n_in,
                              void* d_out, int out_size) {
    const int* tokens = (const int*)d_in[0];
    const float* h0 = (const float*)d_in[1];
    const float* c0 = (const float*)d_in[2];
    const float* embW = (const float*)d_in[3];
    const float* Wih = (const float*)d_in[4];
    const float* Whh = (const float*)d_in[5];
    const float* bih = (const float*)d_in[6];
    const float* bhh = (const float*)d_in[7];
    const float* wq = (const float*)d_in[8];
    const float* bq = (const float*)d_in[9];
    const float* wk = (const float*)d_in[10];
    const float* bk = (const float*)d_in[11];
    const float* wv = (const float*)d_in[12];
    const float* bv = (const float*)d_in[13];
    const float* wfc = (const float*)d_in[14];
    const float* bfc = (const float*)d_in[15];
    const float* lng = (const float*)d_in[16];
    const float* lnb = (const float*)d_in[17];
    const float* Wd = (const float*)d_in[18];
    const float* bd = (const float*)d_in[19];
    float* out = (float*)d_out;

    static int attr_set = 0;
    if (!attr_set) {
        cudaFuncSetAttribute(k_rec, cudaFuncAttributeMaxDynamicSharedMemorySize,
                             SMEM_REC);
        cudaFuncSetAttribute(k_mma<true>, cudaFuncAttributeMaxDynamicSharedMemorySize,
                             DEC_SMEM);
        cudaFuncSetAttribute(k_mma<false>, cudaFuncAttributeMaxDynamicSharedMemorySize,
                             DEC_SMEM);
        attr_set = 1;
    }

    float *xg, *hbuf, *hlbuf;
    unsigned short *wh, *wl, *xh, *xl, *yh, *yl, *wihh, *wihl;
    cudaGetSymbolAddress((void**)&xg, g_xg);
    cudaGetSymbolAddress((void**)&hbuf, g_h);
    cudaGetSymbolAddress((void**)&hlbuf, g_hl);
    cudaGetSymbolAddress((void**)&wh, g_wh);
    cudaGetSymbolAddress((void**)&wl, g_wl);
    cudaGetSymbolAddress((void**)&xh, g_xh);
    cudaGetSymbolAddress((void**)&xl, g_xl);
    cudaGetSymbolAddress((void**)&yh, g_yh);
    cudaGetSymbolAddress((void**)&yl, g_yl);
    cudaGetSymbolAddress((void**)&wihh, g_wihh);
    cudaGetSymbolAddress((void**)&wihl, g_wihl);

    // weight conversions (fp16 hi/lo planes)
    k_cvt<<<(int)(((size_t)NTOK * NHID / 4) / 256), 256>>>((const float4*)Wd, wh, wl);
    k_cvt<<<(int)(((size_t)NLAYERS * NB * 4 * BS * NINP / 4) / 256), 256>>>(
        (const float4*)Wih, wihh, wihl);

    // embedding -> plane buffer A
    k_embed<<<T * B, 256>>>(tokens, embW, xh, xl);

    const size_t DECN = (size_t)T * B * NTOK;
    const size_t WIH_L = (size_t)NB * 4 * BS * NINP;
    for (int l = 0; l < NLAYERS; ++l) {
        unsigned short* inh = (l == 0) ? xh : yh;
        unsigned short* inl = (l == 0) ? xl : yl;
        unsigned short* outh = (l == 0) ? yh : xh;
        unsigned short* outl = (l == 0) ? yl : xl;
        const float* Whh_l = Whh + (size_t)l * NB * 4 * BS * BS;
        const float* bih_l = bih + (size_t)l * NB * 4 * BS;
        const float* bhh_l = bhh + (size_t)l * NB * 4 * BS;
        // xg = xin @ Wih_l^T on tensor cores (fp16 3-term)
        k_mma<true><<<dim3(32, 32), 256, DEC_SMEM>>>(inh, inl, wihh + l * WIH_L,
                                                     wihl + l * WIH_L, nullptr, xg,
                                                     NB * 4 * BS);
        k_rec<<<NCTA, 256, SMEM_REC>>>(xg, Whh_l, bih_l, bhh_l,
                                       h0 + (size_t)l * B * NHID,
                                       c0 + (size_t)l * B * NHID,
                                       wq, bq, wk, bk, wv, bv, wfc, bfc, lng, lnb,
                                       hbuf, hlbuf, outh, outl,
                                       out + DECN + (size_t)l * B * NHID,
                                       out + DECN + (size_t)NLAYERS * B * NHID +
                                           (size_t)l * B * NHID);
    }
    // decoder: out = X @ Wd^T + bd (fp16 2-term; X planes = layer-1 outputs in A)
    k_mma<false><<<dim3(32, 250), 256, DEC_SMEM>>>(xh, xl, wh, wl, bd, out, NTOK);
}

// round 15
// speedup vs baseline: 1.2787x; 1.1006x over previous
#include <cuda_runtime.h>
#include <cuda_fp16.h>
#include <cstdint>

#define NLAYERS 2
#define NB 4
#define BS 256
#define NHID 1024
#define NINP 1024
#define NTOK 32000
#define T 64
#define B 64
#define DK 16
#define NCTA 128

// ---------------- scratch (device globals: no allocation allowed) ----------
__device__ float g_xg[(size_t)T * B * NB * 4 * BS];
__device__ float g_h[B * NHID];
__device__ float g_hl[B * NHID];
__device__ unsigned g_flags[2 * NCTA * 32];           // per-group, one flag/128B line
__device__ unsigned short g_wh[(size_t)NTOK * NHID];  // Wd fp16 hi
__device__ unsigned short g_wl[(size_t)NTOK * NHID];  // Wd fp16 lo
__device__ unsigned short g_xh[(size_t)T * B * NHID]; // plane buffer A hi
__device__ unsigned short g_xl[(size_t)T * B * NHID]; // plane buffer A lo
__device__ unsigned short g_yh[(size_t)T * B * NHID]; // plane buffer B hi
__device__ unsigned short g_yl[(size_t)T * B * NHID]; // plane buffer B lo
__device__ unsigned short g_wihh[(size_t)NLAYERS * NB * 4 * BS * NINP]; // Wih hi
__device__ unsigned short g_wihl[(size_t)NLAYERS * NB * 4 * BS * NINP]; // Wih lo

// ---------------- f32x2 helpers ---------------------------------------------
__device__ __forceinline__ unsigned long long splat2(float a) {
    unsigned long long r;
    unsigned int u = __float_as_uint(a);
    asm("mov.b64 %0, {%1, %1};" : "=l"(r) : "r"(u));
    return r;
}
__device__ __forceinline__ unsigned long long pack2(float x, float y) {
    unsigned long long r;
    asm("mov.b64 %0, {%1, %2};" : "=l"(r)
        : "r"(__float_as_uint(x)), "r"(__float_as_uint(y)));
    return r;
}
__device__ __forceinline__ void ffma2(unsigned long long &c, unsigned long long a,
                                      unsigned long long b) {
    asm("fma.rn.f32x2 %0, %1, %2, %0;" : "+l"(c) : "l"(a), "l"(b));
}
__device__ __forceinline__ float2 unpk(unsigned long long v) {
    unsigned int x, y;
    asm("mov.b64 {%0, %1}, %2;" : "=r"(x), "=r"(y) : "l"(v));
    return make_float2(__uint_as_float(x), __uint_as_float(y));
}
__device__ __forceinline__ float sigmoidf_(float x) { return 1.f / (1.f + expf(-x)); }

// ---------------- dummy (shifts ncu capture slot onto k_rec) -----------------
__global__ void k_dummy() {}

// ---------------- fp32 -> (hi, lo) fp16 split precompute (weights) -----------
__global__ void k_cvt(const float4* __restrict__ src,
                      unsigned short* __restrict__ hi,
                      unsigned short* __restrict__ lo) {
    size_t idx = (size_t)blockIdx.x * blockDim.x + threadIdx.x;
    float4 v = src[idx];
    float f[4] = {v.x, v.y, v.z, v.w};
    __half h[4], l[4];
#pragma unroll
    for (int i = 0; i < 4; ++i) {
        h[i] = __float2half_rn(f[i]);
        l[i] = __float2half_rn(f[i] - __half2float(h[i]));
    }
    uint2 hp, lp;
    hp.x = ((uint32_t)*(unsigned short*)&h[1] << 16) | *(unsigned short*)&h[0];
    hp.y = ((uint32_t)*(unsigned short*)&h[3] << 16) | *(unsigned short*)&h[2];
    lp.x = ((uint32_t)*(unsigned short*)&l[1] << 16) | *(unsigned short*)&l[0];
    lp.y = ((uint32_t)*(unsigned short*)&l[3] << 16) | *(unsigned short*)&l[2];
    *(uint2*)(hi + idx * 4) = hp;
    *(uint2*)(lo + idx * 4) = lp;
}

// ---------------- HMMA fp16 + ldmatrix + cp.async helpers --------------------
__device__ __forceinline__ void mma16816(float* d, uint32_t a0, uint32_t a1,
                                         uint32_t a2, uint32_t a3,
                                         uint32_t b0, uint32_t b1) {
    asm volatile(
        "mma.sync.aligned.m16n8k16.row.col.f32.f16.f16.f32 "
        "{%0,%1,%2,%3},{%4,%5,%6,%7},{%8,%9},{%0,%1,%2,%3};"
        : "+f"(d[0]), "+f"(d[1]), "+f"(d[2]), "+f"(d[3])
        : "r"(a0), "r"(a1), "r"(a2), "r"(a3), "r"(b0), "r"(b1));
}
__device__ __forceinline__ uint32_t smem_u32(const void* p) {
    uint32_t a;
    asm("{ .reg .u64 t; cvta.to.shared.u64 t, %1; cvt.u32.u64 %0, t; }"
        : "=r"(a) : "l"(p));
    return a;
}
__device__ __forceinline__ void ldsm4(uint32_t &r0, uint32_t &r1, uint32_t &r2,
                                      uint32_t &r3, uint32_t addr) {
    asm volatile("ldmatrix.sync.aligned.m8n8.x4.shared.b16 {%0,%1,%2,%3},[%4];"
                 : "=r"(r0), "=r"(r1), "=r"(r2), "=r"(r3) : "r"(addr));
}
__device__ __forceinline__ void ldsm2(uint32_t &r0, uint32_t &r1, uint32_t addr) {
    asm volatile("ldmatrix.sync.aligned.m8n8.x2.shared.b16 {%0,%1},[%2];"
                 : "=r"(r0), "=r"(r1) : "r"(addr));
}
__device__ __forceinline__ void cpasync16(uint32_t dst, const void* src) {
    asm volatile("cp.async.cg.shared.global [%0], [%1], 16;"
                 :: "r"(dst), "l"(src) : "memory");
}
#define CP_COMMIT() asm volatile("cp.async.commit_group;" ::: "memory")
#define CP_WAIT1() asm volatile("cp.async.wait_group 1;" ::: "memory")
#define CP_WAIT0() asm volatile("cp.async.wait_group 0;" ::: "memory")

// ---------------- tensor-core GEMM (fp16 split, cp.async pipeline) -----------
// THREE=true : D = Ah*Bh + Ah*Bl + Al*Bh (3-term; for xg). 2-stage, 40KB bufs.
// THREE=false: D = Ah*Bh + Ah*Bl        (2-term; decoder). 3-stage, 30KB bufs.
#define SMEM_MMA3 (2 * 40960)
#define SMEM_MMA2 (3 * 30720)
template <bool THREE>
__global__ void __launch_bounds__(256, 2) k_mma(
    const unsigned short* __restrict__ Xh, const unsigned short* __restrict__ Xl,
    const unsigned short* __restrict__ Wh, const unsigned short* __restrict__ Wl,
    const float* __restrict__ bias, float* __restrict__ out, int ldc) {
    extern __shared__ char sm[];
    const uint32_t sbase = smem_u32(sm);
    const uint32_t BUF = THREE ? 40960u : 30720u;   // per-stage bytes
    const uint32_t BOFF = THREE ? 20480u : 10240u;  // Bh plane offset
    const int tid = threadIdx.x;
    const int wid = tid >> 5, lid = tid & 31;
    const int m0 = blockIdx.x * 128;
    const int n0 = blockIdx.y * 128;
    const int warpM = wid >> 2;
    const int warpN = wid & 3;
    const int laneR = lid >> 2;
    const int laneC2 = (lid & 3) * 2;
    const uint32_t aoff = (uint32_t)((lid & 15) * 80 + (lid >> 4) * 16);
    const uint32_t boff = (uint32_t)((lid & 7) * 80 + ((lid >> 3) & 1) * 16);

    const int lrow = tid >> 1;
    const int lseg = tid & 1;
    const unsigned short* arh = Xh + (size_t)(m0 + lrow) * 1024 + lseg * 16;
    const unsigned short* arl = Xl + (size_t)(m0 + lrow) * 1024 + lseg * 16;
    const unsigned short* brh = Wh + (size_t)(n0 + lrow) * 1024 + lseg * 16;
    const unsigned short* brl = Wl + (size_t)(n0 + lrow) * 1024 + lseg * 16;
    const uint32_t sdst = sbase + (uint32_t)(lrow * 80 + lseg * 32);

    float acc[4][4][4];
#pragma unroll
    for (int a = 0; a < 4; ++a)
#pragma unroll
        for (int b = 0; b < 4; ++b)
#pragma unroll
            for (int c = 0; c < 4; ++c) acc[a][b][c] = 0.f;

    auto issue = [&](int kc, int b) {
        uint32_t base = sdst + (uint32_t)b * BUF;
        int koff = kc * 32;
        cpasync16(base, arh + koff);
        cpasync16(base + 16, arh + koff + 8);
        if (THREE) {
            cpasync16(base + 10240, arl + koff);
            cpasync16(base + 10240 + 16, arl + koff + 8);
        }
        cpasync16(base + BOFF, brh + koff);
        cpasync16(base + BOFF + 16, brh + koff + 8);
        cpasync16(base + BOFF + 10240, brl + koff);
        cpasync16(base + BOFF + 10240 + 16, brl + koff + 8);
        CP_COMMIT();
    };
    issue(0, 0);
    issue(1, 1);

    const int NCH = 1024 / 32;
    for (int kc = 0; kc < NCH; ++kc) {
        if (kc < NCH - 1) { CP_WAIT1(); } else { CP_WAIT0(); }
        __syncthreads();
        const uint32_t bufoff = (uint32_t)(THREE ? (kc & 1) : (kc % 3)) * BUF;
#pragma unroll
        for (int ks = 0; ks < 2; ++ks) {
            uint32_t ah[4][4], al[4][4], bh[4][2], bl[4][2];
#pragma unroll
            for (int mt = 0; mt < 4; ++mt) {
                uint32_t ad = sbase + bufoff +
                              (uint32_t)((warpM * 64 + mt * 16) * 80 + ks * 32) + aoff;
                ldsm4(ah[mt][0], ah[mt][1], ah[mt][2], ah[mt][3], ad);
                if (THREE)
                    ldsm4(al[mt][0], al[mt][1], al[mt][2], al[mt][3], ad + 10240);
            }
#pragma unroll
            for (int nt = 0; nt < 4; ++nt) {
                uint32_t bd_ = sbase + bufoff + BOFF +
                               (uint32_t)((warpN * 32 + nt * 8) * 80 + ks * 32) + boff;
                ldsm2(bh[nt][0], bh[nt][1], bd_);
                ldsm2(bl[nt][0], bl[nt][1], bd_ + 10240);
            }
#pragma unroll
            for (int mt = 0; mt < 4; ++mt)
#pragma unroll
                for (int nt = 0; nt < 4; ++nt)
                    mma16816(acc[mt][nt], ah[mt][0], ah[mt][1], ah[mt][2], ah[mt][3],
                             bh[nt][0], bh[nt][1]);
#pragma unroll
            for (int mt = 0; mt < 4; ++mt)
#pragma unroll
                for (int nt = 0; nt < 4; ++nt)
                    mma16816(acc[mt][nt], ah[mt][0], ah[mt][1], ah[mt][2], ah[mt][3],
                             bl[nt][0], bl[nt][1]);
            if (THREE) {
#pragma unroll
                for (int mt = 0; mt < 4; ++mt)
#pragma unroll
                    for (int nt = 0; nt < 4; ++nt)
                        mma16816(acc[mt][nt], al[mt][0], al[mt][1], al[mt][2],
                                 al[mt][3], bh[nt][0], bh[nt][1]);
            }
        }
        if (THREE) {
            // 2-stage: next issue overwrites the buffer just consumed
            __syncthreads();
            if (kc + 2 < NCH) issue(kc + 2, kc & 1);
        } else {
            // 3-stage: issue targets buffer consumed at kc-1; all warps are past
            // the top-of-kc barrier (hence past kc-1's compute) -> no extra sync
            if (kc + 2 < NCH) issue(kc + 2, (kc + 2) % 3);
        }
    }

#pragma unroll
    for (int mt = 0; mt < 4; ++mt) {
        int m = m0 + warpM * 64 + mt * 16 + laneR;
#pragma unroll
        for (int nt = 0; nt < 4; ++nt) {
            int n = n0 + warpN * 32 + nt * 8 + laneC2;
            float bx = 0.f, by = 0.f;
            if (bias) { bx = bias[n]; by = bias[n + 1]; }
            *(float2*)(out + (size_t)m * ldc + n) =
                make_float2(acc[mt][nt][0] + bx, acc[mt][nt][1] + by);
            *(float2*)(out + (size_t)(m + 8) * ldc + n) =
                make_float2(acc[mt][nt][2] + bx, acc[mt][nt][3] + by);
        }
    }
}

// ---------------- embedding gather -> fp16 hi/lo planes ----------------------
__global__ void k_embed(const int* __restrict__ tokens, const float* __restrict__ embW,
                        unsigned short* __restrict__ xh,
                        unsigned short* __restrict__ xl) {
    int tb = blockIdx.x;
    int tok = tokens[tb];
    int tid = threadIdx.x;
    float4 v = *(const float4*)(embW + (size_t)tok * NINP + tid * 4);
    float f[4] = {v.x, v.y, v.z, v.w};
    __half h[4], l[4];
#pragma unroll
    for (int i = 0; i < 4; ++i) {
        h[i] = __float2half_rn(f[i]);
        l[i] = __float2half_rn(f[i] - __half2float(h[i]));
    }
    uint2 hp, lp;
    hp.x = ((uint32_t)*(unsigned short*)&h[1] << 16) | *(unsigned short*)&h[0];
    hp.y = ((uint32_t)*(unsigned short*)&h[3] << 16) | *(unsigned short*)&h[2];
    lp.x = ((uint32_t)*(unsigned short*)&l[1] << 16) | *(unsigned short*)&l[0];
    lp.y = ((uint32_t)*(unsigned short*)&l[3] << 16) | *(unsigned short*)&l[2];
    size_t base = (size_t)tb * NINP + tid * 4;
    *(uint2*)(xh + base) = hp;
    *(uint2*)(xl + base) = lp;
}

// ---------------- persistent recurrence v4 (warp-specialized groups) ---------
#define SMEM_REC (45184 * 4)
__global__ void __launch_bounds__(256, 1) k_rec(
    const float* __restrict__ xg, const float* __restrict__ Whh_l,
    const float* __restrict__ bih_l, const float* __restrict__ bhh_l,
    const float* __restrict__ h0_l, const float* __restrict__ c0_l,
    const float* __restrict__ wq, const float* __restrict__ bq,
    const float* __restrict__ wk, const float* __restrict__ bk,
    const float* __restrict__ wv, const float* __restrict__ bv,
    const float* __restrict__ wfc, const float* __restrict__ bfc,
    const float* __restrict__ lng, const float* __restrict__ lnb,
    float* __restrict__ hbuf, float* __restrict__ hlbuf,
    unsigned short* __restrict__ ysh, unsigned short* __restrict__ ysl,
    float* __restrict__ outH, float* __restrict__ outC) {
    extern __shared__ float smf[];
    float* swf  = smf;             // Whh slice [256 k][36 cols]    9216
    float* smw  = smf + 28032;     // q/k/v weights [48][256]       12288
    float* swfc = smf + 40320;     // wfc [256][16]                 4096
    float* sbfc = smf + 44416;
    float* slng = smf + 44672;
    float* slnb = smf + 44928;

    __shared__ float sq2[2][DK], skk2[2][NB][DK], svv2[2][NB][DK];
    __shared__ float ssc2[2][NB], sp2[2][NB], so2[2][DK], sredh[2][4];

    const int tid = threadIdx.x;
    const int r = blockIdx.x;
    const int n = r & 3;
    const int j0 = (r >> 2) * 8;
    const int g = tid >> 7;
    const int lt = tid & 127;
    const int tj = lt & 7, tb2l = lt >> 3;
    const int j = j0 + tj;
    const int lane = tid & 31;
    const int bA = g * 32 + tb2l * 2;

    float* sg = smf + 9216 + g * 8320;
    float* sh = smf + 25856 + g * 1088;

    {
        const float* W = Whh_l + (size_t)n * 4 * BS * BS;
#pragma unroll
        for (int e = 0; e < 8; ++e) {
            int idx = e * 256 + tid;
            int col = idx >> 6, kq = idx & 63;
            int gg = col & 3, jj = col >> 2;
            float4 v = *(const float4*)(W + (size_t)(gg * BS + j0 + jj) * BS + kq * 4);
            swf[(kq * 4 + 0) * 36 + col] = v.x;
            swf[(kq * 4 + 1) * 36 + col] = v.y;
            swf[(kq * 4 + 2) * 36 + col] = v.z;
            swf[(kq * 4 + 3) * 36 + col] = v.w;
        }
#pragma unroll
        for (int i = 0; i < 4; ++i) {
            ((float4*)smw)[tid + i * 256] = ((const float4*)wq)[tid + i * 256];
            ((float4*)(smw + 4096))[tid + i * 256] = ((const float4*)wk)[tid + i * 256];
            ((float4*)(smw + 8192))[tid + i * 256] = ((const float4*)wv)[tid + i * 256];
            ((float4*)swfc)[tid + i * 256] = ((const float4*)wfc)[tid + i * 256];
        }
        sbfc[tid] = bfc[tid];
        slng[tid] = lng[tid];
        slnb[tid] = lnb[tid];
    }

    const float b_i = bih_l[n * 4 * BS + 0 * BS + j] + bhh_l[n * 4 * BS + 0 * BS + j];
    const float b_f = bih_l[n * 4 * BS + 1 * BS + j] + bhh_l[n * 4 * BS + 1 * BS + j];
    const float b_g = bih_l[n * 4 * BS + 2 * BS + j] + bhh_l[n * 4 * BS + 2 * BS + j];
    const float b_o = bih_l[n * 4 * BS + 3 * BS + j] + bhh_l[n * 4 * BS + 3 * BS + j];
    float creg[2];
    creg[0] = c0_l[(bA + 0) * NHID + n * BS + j];
    creg[1] = c0_l[(bA + 1) * NHID + n * BS + j];

    unsigned* flags = g_flags + (size_t)g * NCTA * 32;
    unsigned bgen = flags[r * 32];

    {
        int base = (r * 256 + tid) * 2;
        float2 v = *(const float2*)(h0_l + base);
        __stcg((float2*)(hbuf + base), v);
    }

    float xgv[2][4];
    {
#pragma unroll
        for (int bi = 0; bi < 2; ++bi) {
            const float* xr = xg + (size_t)(bA + bi) * 4096 + n * 1024 + j;
            xgv[bi][0] = __ldg(xr);       xgv[bi][1] = __ldg(xr + 256);
            xgv[bi][2] = __ldg(xr + 512); xgv[bi][3] = __ldg(xr + 768);
        }
    }
    __syncthreads();

#define HBAR() asm volatile("bar.sync %0, 128;" :: "r"(g + 1) : "memory")
    auto gbar = [&]() {
        HBAR();
        ++bgen;
        if (lt == 0) {
            asm volatile("st.release.gpu.global.u32 [%0], %1;"
                         :: "l"(&flags[r * 32]), "r"(bgen) : "memory");
        }
        {
            unsigned v;
            do {
                asm volatile("ld.acquire.gpu.global.u32 %0, [%1];"
                             : "=r"(v) : "l"(&flags[lt * 32]) : "memory");
            } while (v < bgen);
        }
        HBAR();
    };
    gbar();

    const int nn2 = r & 3;
    const int bb2 = g * 32 + (r >> 2);

    for (int t = 0; t < T; ++t) {
#pragma unroll 4
        for (int i = 0; i < 16; ++i) {
            int idx = lt + i * 128;
            int bbl = idx >> 6, kq = idx & 63;
            float4 v = __ldcg((const float4*)(hbuf +
                              (size_t)(g * 32 + bbl) * NHID + n * BS) + kq);
            *(float4*)&sg[bbl * 260 + kq * 4] = v;
        }
        HBAR();

        unsigned long long a00 = pack2(xgv[0][0] + b_i, xgv[0][1] + b_f);
        unsigned long long a01 = pack2(xgv[0][2] + b_g, xgv[0][3] + b_o);
        unsigned long long a10 = pack2(xgv[1][0] + b_i, xgv[1][1] + b_f);
        unsigned long long a11 = pack2(xgv[1][2] + b_g, xgv[1][3] + b_o);
        const float* s0 = &sg[(tb2l * 2 + 0) * 260];
        const float* s1 = &sg[(tb2l * 2 + 1) * 260];
        const float* wrow = &swf[tj * 4];
#pragma unroll 8
        for (int k = 0; k < 256; ++k) {
            ulonglong2 wv = *(const ulonglong2*)(wrow + k * 36);
            unsigned long long as0 = splat2(s0[k]);
            unsigned long long as1 = splat2(s1[k]);
            ffma2(a00, as0, wv.x); ffma2(a01, as0, wv.y);
            ffma2(a10, as1, wv.x); ffma2(a11, as1, wv.y);
        }
        {
            float2 g01 = unpk(a00), g23 = unpk(a01);
            float cn = sigmoidf_(g01.y) * creg[0] + sigmoidf_(g01.x) * tanhf(g23.x);
            creg[0] = cn;
            __stcg(hlbuf + (size_t)(bA + 0) * NHID + n * BS + j,
                   sigmoidf_(g23.y) * tanhf(cn));
            g01 = unpk(a10); g23 = unpk(a11);
            cn = sigmoidf_(g01.y) * creg[1] + sigmoidf_(g01.x) * tanhf(g23.x);
            creg[1] = cn;
            __stcg(hlbuf + (size_t)(bA + 1) * NHID + n * BS + j,
                   sigmoidf_(g23.y) * tanhf(cn));
        }
        gbar();

        {
            const float4* src = (const float4*)(hlbuf + (size_t)bb2 * NHID);
            ((float4*)sh)[lt] = __ldcg(src + lt);
            ((float4*)sh)[lt + 128] = __ldcg(src + lt + 128);
        }
        HBAR();
        for (int w = lt; w < 144; w += 128) {
            const float *hv, *wr; float* dst; float bpv;
            if (w < 16) { wr = smw + w * 256; hv = sh + nn2 * 256;
                          dst = &sq2[g][w]; bpv = __ldg(bq + w); }
            else if (w < 80) { int m = (w - 16) >> 4, d = (w - 16) & 15;
                               wr = smw + 4096 + d * 256; hv = sh + m * 256;
                               dst = &skk2[g][m][d]; bpv = __ldg(bk + d); }
            else { int m = (w - 80) >> 4, d = (w - 80) & 15;
                   wr = smw + 8192 + d * 256; hv = sh + m * 256;
                   dst = &svv2[g][m][d]; bpv = __ldg(bv + d); }
            float a0 = 0, a1 = 0, a2 = 0, a3 = 0;
#pragma unroll
            for (int jj = 0; jj < 256; jj += 8) {
                float4 h4 = *(const float4*)(hv + jj);
                float4 w4 = *(const float4*)(wr + jj);
                float4 h5 = *(const float4*)(hv + jj + 4);
                float4 w5 = *(const float4*)(wr + jj + 4);
                a0 += h4.x * w4.x + h5.x * w5.x;
                a1 += h4.y * w4.y + h5.y * w5.y;
                a2 += h4.z * w4.z + h5.z * w5.z;
                a3 += h4.w * w4.w + h5.w * w5.w;
            }
            *dst = a0 + a1 + a2 + a3 + bpv;
        }
        HBAR();
        if (lt < 4) {
            float s = 0;
#pragma unroll
            for (int d = 0; d < DK; ++d) s += sq2[g][d] * skk2[g][lt][d];
            ssc2[g][lt] = s * 0.25f;
        }
        HBAR();
        if (lt < 4) {
            float mx = fmaxf(fmaxf(ssc2[g][0], ssc2[g][1]),
                             fmaxf(ssc2[g][2], ssc2[g][3]));
            float sum = expf(ssc2[g][0] - mx) + expf(ssc2[g][1] - mx) +
                        expf(ssc2[g][2] - mx) + expf(ssc2[g][3] - mx);
            sp2[g][lt] = expf(ssc2[g][lt] - mx) / sum;
        }
        HBAR();
        if (lt < DK) {
            float o = 0;
#pragma unroll
            for (int m = 0; m < NB; ++m) o += sp2[g][m] * svv2[g][m][lt];
            so2[g][lt] = o;
        }
        HBAR();
        float v0 = sbfc[lt] + sh[nn2 * 256 + lt];
        float v1 = sbfc[lt + 128] + sh[nn2 * 256 + lt + 128];
#pragma unroll
        for (int d = 0; d < DK; ++d) {
            v0 += so2[g][d] * swfc[lt * DK + d];
            v1 += so2[g][d] * swfc[(lt + 128) * DK + d];
        }
        float s = v0 + v1;
#pragma unroll
        for (int off = 16; off; off >>= 1) s += __shfl_down_sync(0xffffffffu, s, off);
        if (lane == 0) sredh[g][lt >> 5] = s;
        HBAR();
        float mu = (sredh[g][0] + sredh[g][1] + sredh[g][2] + sredh[g][3])
                   * (1.f / BS);
        HBAR();
        float dv0 = v0 - mu, dv1 = v1 - mu;
        float s2 = dv0 * dv0 + dv1 * dv1;
#pragma unroll
        for (int off = 16; off; off >>= 1) s2 += __shfl_down_sync(0xffffffffu, s2, off);
        if (lane == 0) sredh[g][lt >> 5] = s2;
        HBAR();
        float var = (sredh[g][0] + sredh[g][1] + sredh[g][2] + sredh[g][3])
                    * (1.f / BS);
        float rstd = rsqrtf(var + 1e-5f);
        float y0 = dv0 * rstd * slng[lt] + slnb[lt];
        float y1 = dv1 * rstd * slng[lt + 128] + slnb[lt + 128];
        int i0 = bb2 * NHID + nn2 * 256 + lt;
        __stcg(hbuf + i0, y0);
        __stcg(hbuf + i0 + 128, y1);
        {
            unsigned short* ysh_t = ysh + (size_t)t * B * NHID;
            unsigned short* ysl_t = ysl + (size_t)t * B * NHID;
            __half h0_ = __float2half_rn(y0);
            __half l0_ = __float2half_rn(y0 - __half2float(h0_));
            __half h1_ = __float2half_rn(y1);
            __half l1_ = __float2half_rn(y1 - __half2float(h1_));
            ysh_t[i0] = *(unsigned short*)&h0_;
            ysl_t[i0] = *(unsigned short*)&l0_;
            ysh_t[i0 + 128] = *(unsigned short*)&h1_;
            ysl_t[i0 + 128] = *(unsigned short*)&l1_;
        }

        if (t + 1 < T) {
            const float* xg_t = xg + (size_t)(t + 1) * B * 4096;
#pragma unroll
            for (int bi = 0; bi < 2; ++bi) {
                const float* xr = xg_t + (size_t)(bA + bi) * 4096 + n * 1024 + j;
                xgv[bi][0] = __ldg(xr);       xgv[bi][1] = __ldg(xr + 256);
                xgv[bi][2] = __ldg(xr + 512); xgv[bi][3] = __ldg(xr + 768);
            }
        }
        gbar();
    }

    __syncthreads();
    {
        int base = (r * 256 + tid) * 2;
        float2 v = __ldcg((const float2*)(hbuf + base));
        *(float2*)(outH + base) = v;
    }
    outC[(bA + 0) * NHID + n * BS + j] = creg[0];
    outC[(bA + 1) * NHID + n * BS + j] = creg[1];
#undef HBAR
}

// ---------------- host driver ------------------------------------------------
extern "C" void kernel_launch(void* const* d_in, const int* in_sizes, int n_in,
                              void* d_out, int out_size) {
    const int* tokens = (const int*)d_in[0];
    const float* h0 = (const float*)d_in[1];
    const float* c0 = (const float*)d_in[2];
    const float* embW = (const float*)d_in[3];
    const float* Wih = (const float*)d_in[4];
    const float* Whh = (const float*)d_in[5];
    const float* bih = (const float*)d_in[6];
    const float* bhh = (const float*)d_in[7];
    const float* wq = (const float*)d_in[8];
    const float* bq = (const float*)d_in[9];
    const float* wk = (const float*)d_in[10];
    const float* bk = (const float*)d_in[11];
    const float* wv = (const float*)d_in[12];
    const float* bv = (const float*)d_in[13];
    const float* wfc = (const float*)d_in[14];
    const float* bfc = (const float*)d_in[15];
    const float* lng = (const float*)d_in[16];
    const float* lnb = (const float*)d_in[17];
    const float* Wd = (const float*)d_in[18];
    const float* bd = (const float*)d_in[19];
    float* out = (float*)d_out;

    static int attr_set = 0;
    if (!attr_set) {
        cudaFuncSetAttribute(k_rec, cudaFuncAttributeMaxDynamicSharedMemorySize,
                             SMEM_REC);
        cudaFuncSetAttribute(k_mma<true>, cudaFuncAttributeMaxDynamicSharedMemorySize,
                             SMEM_MMA3);
        cudaFuncSetAttribute(k_mma<false>, cudaFuncAttributeMaxDynamicSharedMemorySize,
                             SMEM_MMA2);
        attr_set = 1;
    }

    float *xg, *hbuf, *hlbuf;
    unsigned short *wh, *wl, *xh, *xl, *yh, *yl, *wihh, *wihl;
    cudaGetSymbolAddress((void**)&xg, g_xg);
    cudaGetSymbolAddress((void**)&hbuf, g_h);
    cudaGetSymbolAddress((void**)&hlbuf, g_hl);
    cudaGetSymbolAddress((void**)&wh, g_wh);
    cudaGetSymbolAddress((void**)&wl, g_wl);
    cudaGetSymbolAddress((void**)&xh, g_xh);
    cudaGetSymbolAddress((void**)&xl, g_xl);
    cudaGetSymbolAddress((void**)&yh, g_yh);
    cudaGetSymbolAddress((void**)&yl, g_yl);
    cudaGetSymbolAddress((void**)&wihh, g_wihh);
    cudaGetSymbolAddress((void**)&wihl, g_wihl);

    // dummy launch: shifts ncu capture (-s 5) onto the first k_rec
    k_dummy<<<1, 32>>>();

    // weight conversions (fp16 hi/lo planes)
    k_cvt<<<(int)(((size_t)NTOK * NHID / 4) / 256), 256>>>((const float4*)Wd, wh, wl);
    k_cvt<<<(int)(((size_t)NLAYERS * NB * 4 * BS * NINP / 4) / 256), 256>>>(
        (const float4*)Wih, wihh, wihl);

    // embedding -> plane buffer A
    k_embed<<<T * B, 256>>>(tokens, embW, xh, xl);

    const size_t DECN = (size_t)T * B * NTOK;
    const size_t WIH_L = (size_t)NB * 4 * BS * NINP;
    for (int l = 0; l < NLAYERS; ++l) {
        unsigned short* inh = (l == 0) ? xh : yh;
        unsigned short* inl = (l == 0) ? xl : yl;
        unsigned short* outh = (l == 0) ? yh : xh;
        unsigned short* outl = (l == 0) ? yl : xl;
        const float* Whh_l = Whh + (size_t)l * NB * 4 * BS * BS;
        const float* bih_l = bih + (size_t)l * NB * 4 * BS;
        const float* bhh_l = bhh + (size_t)l * NB * 4 * BS;
        // xg = xin @ Wih_l^T on tensor cores (fp16 3-term)
        k_mma<true><<<dim3(32, 32), 256, SMEM_MMA3>>>(inh, inl, wihh + l * WIH_L,
                                                      wihl + l * WIH_L, nullptr, xg,
                                                      NB * 4 * BS);
        k_rec<<<NCTA, 256, SMEM_REC>>>(xg, Whh_l, bih_l, bhh_l,
                                       h0 + (size_t)l * B * NHID,
                                       c0 + (size_t)l * B * NHID,
                                       wq, bq, wk, bk, wv, bv, wfc, bfc, lng, lnb,
                                       hbuf, hlbuf, outh, outl,
                                       out + DECN + (size_t)l * B * NHID,
                                       out + DECN + (size_t)NLAYERS * B * NHID +
                                           (size_t)l * B * NHID);
    }
    // decoder: out = X @ Wd^T + bd (fp16 2-term; X planes = layer-1 outputs in A)
    k_mma<false><<<dim3(32, 250), 256, SMEM_MMA2>>>(xh, xl, wh, wl, bd, out, NTOK);
}